// round 2
// baseline (speedup 1.0000x reference)
#include <cuda_runtime.h>
#include <cstdint>
#include <math.h>

// Problem dims (fixed by the reference)
#define BB 64
#define TT 512
#define DD 2048
#define H1 256
#define H2 128
#define H3 64

// ---------------- scratch (static device buffers; no allocation) ----------------
__device__ float g_xg1[(size_t)BB * TT * 4 * H1];   // 32768 x 1024
__device__ float g_h1 [(size_t)BB * TT * H1];       // 32768 x 256
__device__ float g_xg2[(size_t)BB * TT * 4 * H2];   // 32768 x 512
__device__ float g_h2 [(size_t)BB * TT * H2];       // 32768 x 128
__device__ float g_xg3[(size_t)BB * TT * 4 * H3];   // 32768 x 256
__device__ float g_h3 [(size_t)BB * H3];            // 64 x 64 (last step only)
__device__ float g_WhhT1[H1 * 4 * H1];              // [256][1024]  (k-major)
__device__ float g_WhhT2[H2 * 4 * H2];              // [128][512]
__device__ float g_WhhT3[H3 * 4 * H3];              // [64][256]

// ---------------- helpers ----------------
__device__ __forceinline__ float to_tf32(float x) {
    uint32_t u;
    asm("cvt.rna.tf32.f32 %0, %1;" : "=r"(u) : "f"(x));
    return __uint_as_float(u);
}

__device__ __forceinline__ void mma_tf32(float* c, const uint32_t* a, const uint32_t* b) {
    asm volatile(
        "mma.sync.aligned.m16n8k8.row.col.f32.tf32.tf32.f32 "
        "{%0,%1,%2,%3}, {%4,%5,%6,%7}, {%8,%9}, {%0,%1,%2,%3};"
        : "+f"(c[0]), "+f"(c[1]), "+f"(c[2]), "+f"(c[3])
        : "r"(a[0]), "r"(a[1]), "r"(a[2]), "r"(a[3]), "r"(b[0]), "r"(b[1]));
}

__device__ __forceinline__ float sigmoidf_(float x) {
    return 1.0f / (1.0f + expf(-x));
}

// ---------------- weight transpose prep ----------------
__global__ void prep_kernel(const float* __restrict__ Whh1,
                            const float* __restrict__ Whh2,
                            const float* __restrict__ Whh3) {
    int idx = blockIdx.x * blockDim.x + threadIdx.x;
    if (idx < 4 * H1 * H1) {   // 1024 x 256
        int r = idx / H1, k = idx % H1;
        g_WhhT1[k * (4 * H1) + r] = Whh1[idx];
    }
    if (idx < 4 * H2 * H2) {   // 512 x 128
        int r = idx / H2, k = idx % H2;
        g_WhhT2[k * (4 * H2) + r] = Whh2[idx];
    }
    if (idx < 4 * H3 * H3) {   // 256 x 64
        int r = idx / H3, k = idx % H3;
        g_WhhT3[k * (4 * H3) + r] = Whh3[idx];
    }
}

// ---------------- tf32 GEMM: C[M,N] = A[M,K] * Bw[N,K]^T + b1[n] + b2[n] ----------------
// BM=128, BN=64, BK=32, 256 threads (8 warps, 4x2 warp grid, 32x32 per warp)
__global__ __launch_bounds__(256) void gemm_tf32_bias(
    const float* __restrict__ A, const float* __restrict__ Bw,
    const float* __restrict__ b1, const float* __restrict__ b2,
    float* __restrict__ C, int M, int N, int K)
{
    constexpr int BM = 128, BN = 64, BK = 32;
    __shared__ float As[BM][BK + 4];
    __shared__ float Bs[BN][BK + 4];

    const int tid  = threadIdx.x;
    const int lane = tid & 31;
    const int warp = tid >> 5;
    const int wm   = warp & 3;   // 0..3
    const int wn   = warp >> 2;  // 0..1
    const int grp  = lane >> 2;  // 0..7
    const int th4  = lane & 3;   // 0..3

    const long bm = (long)blockIdx.x * BM;
    const long bn = (long)blockIdx.y * BN;

    float acc[2][4][4];
#pragma unroll
    for (int i = 0; i < 2; i++)
#pragma unroll
        for (int j = 0; j < 4; j++)
#pragma unroll
            for (int q = 0; q < 4; q++) acc[i][j][q] = 0.0f;

    const int ar = tid >> 3;        // 0..31
    const int ac = (tid & 7) * 4;   // 0..28

    for (int k0 = 0; k0 < K; k0 += BK) {
        // load A tile (128x32)
#pragma unroll
        for (int p = 0; p < 4; ++p) {
            const float4 v = *(const float4*)&A[(bm + ar + p * 32) * (long)K + k0 + ac];
            float4 w;
            w.x = to_tf32(v.x); w.y = to_tf32(v.y); w.z = to_tf32(v.z); w.w = to_tf32(v.w);
            *(float4*)&As[ar + p * 32][ac] = w;
        }
        // load B tile (64x32)
#pragma unroll
        for (int p = 0; p < 2; ++p) {
            const float4 v = *(const float4*)&Bw[(bn + ar + p * 32) * (long)K + k0 + ac];
            float4 w;
            w.x = to_tf32(v.x); w.y = to_tf32(v.y); w.z = to_tf32(v.z); w.w = to_tf32(v.w);
            *(float4*)&Bs[ar + p * 32][ac] = w;
        }
        __syncthreads();

#pragma unroll
        for (int kk = 0; kk < BK; kk += 8) {
            uint32_t afr[2][4];
#pragma unroll
            for (int ms = 0; ms < 2; ++ms) {
                const int mr = wm * 32 + ms * 16 + grp;
                afr[ms][0] = __float_as_uint(As[mr    ][kk + th4    ]);
                afr[ms][1] = __float_as_uint(As[mr + 8][kk + th4    ]);
                afr[ms][2] = __float_as_uint(As[mr    ][kk + th4 + 4]);
                afr[ms][3] = __float_as_uint(As[mr + 8][kk + th4 + 4]);
            }
            uint32_t bfr[4][2];
#pragma unroll
            for (int ns = 0; ns < 4; ++ns) {
                const int nc = wn * 32 + ns * 8 + grp;
                bfr[ns][0] = __float_as_uint(Bs[nc][kk + th4    ]);
                bfr[ns][1] = __float_as_uint(Bs[nc][kk + th4 + 4]);
            }
#pragma unroll
            for (int ms = 0; ms < 2; ++ms)
#pragma unroll
                for (int ns = 0; ns < 4; ++ns)
                    mma_tf32(acc[ms][ns], afr[ms], bfr[ns]);
        }
        __syncthreads();
    }

    // epilogue with bias
#pragma unroll
    for (int ms = 0; ms < 2; ++ms) {
#pragma unroll
        for (int ns = 0; ns < 4; ++ns) {
            const long r0 = bm + wm * 32 + ms * 16 + grp;
            const long c0 = bn + wn * 32 + ns * 8 + 2 * th4;
            const float bias0 = b1[c0] + b2[c0];
            const float bias1 = b1[c0 + 1] + b2[c0 + 1];
            C[r0 * N + c0]           = acc[ms][ns][0] + bias0;
            C[r0 * N + c0 + 1]       = acc[ms][ns][1] + bias1;
            C[(r0 + 8) * N + c0]     = acc[ms][ns][2] + bias0;
            C[(r0 + 8) * N + c0 + 1] = acc[ms][ns][3] + bias1;
        }
    }
}

// ---------------- LSTM recurrence: one CTA per batch element ----------------
// xg: [B, T, 4H] precomputed input projections (+both biases)
// WhhT: [H][4H] (k-major transposed recurrent weights)
// hout: [B,T,H] if !LAST_ONLY else [B,H]
template <int H, bool LAST_ONLY>
__global__ void lstm_kernel(const float* __restrict__ xg,
                            const float* __restrict__ WhhT,
                            float* __restrict__ hout)
{
    constexpr int G = 4 * H;
    __shared__ float h_s[H];
    __shared__ float g_s[G];

    const int j = threadIdx.x;      // 0..H-1; owns gate rows 4j..4j+3 in phase 1, h-index j in phase 2
    const int b = blockIdx.x;

    h_s[j] = 0.0f;
    float c_reg = 0.0f;
    __syncthreads();

    const size_t base = (size_t)b * TT * G;
    const int gate = j / (H / 4);   // rows 4j..4j+3 all in this gate

    for (int t = 0; t < TT; ++t) {
        float4 acc = *(const float4*)(xg + base + (size_t)t * G + 4 * j);

#pragma unroll 8
        for (int k = 0; k < H; ++k) {
            const float hk = h_s[k];
            const float4 w = *(const float4*)(WhhT + (size_t)k * G + 4 * j);
            acc.x = fmaf(w.x, hk, acc.x);
            acc.y = fmaf(w.y, hk, acc.y);
            acc.z = fmaf(w.z, hk, acc.z);
            acc.w = fmaf(w.w, hk, acc.w);
        }

        float4 a4;
        if (gate == 2) {
            a4.x = tanhf(acc.x); a4.y = tanhf(acc.y);
            a4.z = tanhf(acc.z); a4.w = tanhf(acc.w);
        } else {
            a4.x = sigmoidf_(acc.x); a4.y = sigmoidf_(acc.y);
            a4.z = sigmoidf_(acc.z); a4.w = sigmoidf_(acc.w);
        }
        g_s[4 * j + 0] = a4.x;
        g_s[4 * j + 1] = a4.y;
        g_s[4 * j + 2] = a4.z;
        g_s[4 * j + 3] = a4.w;
        __syncthreads();

        const float iv = g_s[j];
        const float fv = g_s[H + j];
        const float gv = g_s[2 * H + j];
        const float ov = g_s[3 * H + j];
        c_reg = fv * c_reg + iv * gv;
        const float h = ov * tanhf(c_reg);
        h_s[j] = h;

        if (!LAST_ONLY) {
            hout[((size_t)b * TT + t) * H + j] = h;
        } else if (t == TT - 1) {
            hout[(size_t)b * H + j] = h;
        }
        __syncthreads();
    }
}

// ---------------- head: deep/wide/concat/output ----------------
__global__ void head_kernel(const float* __restrict__ x,
                            const float* __restrict__ h3last,
                            const float* __restrict__ Wd, const float* __restrict__ bd,
                            const float* __restrict__ Ww, const float* __restrict__ bw,
                            const float* __restrict__ Wo, const float* __restrict__ bo,
                            float* __restrict__ out)
{
    const int b = blockIdx.x;
    const int j = threadIdx.x;  // 0..31

    // wide: relu(x[b,-1,:] @ Ww[j]^T + bw[j])
    const float* xrow = x + ((size_t)b * TT + (TT - 1)) * DD;
    const float* wwr = Ww + (size_t)j * DD;
    float wide = bw[j];
    for (int k = 0; k < DD; ++k) wide = fmaf(xrow[k], wwr[k], wide);
    wide = fmaxf(wide, 0.0f);

    // deep: relu(h3last[b] @ Wd[j]^T + bd[j])
    const float* hrow = h3last + (size_t)b * H3;
    const float* wdr = Wd + (size_t)j * H3;
    float deep = bd[j];
#pragma unroll
    for (int k = 0; k < H3; ++k) deep = fmaf(hrow[k], wdr[k], deep);
    deep = fmaxf(deep, 0.0f);

    float v = deep * Wo[j] + wide * Wo[32 + j];
#pragma unroll
    for (int off = 16; off > 0; off >>= 1)
        v += __shfl_xor_sync(0xffffffffu, v, off);
    if (j == 0) out[b] = v + bo[0];
}

// ---------------- launch ----------------
extern "C" void kernel_launch(void* const* d_in, const int* in_sizes, int n_in,
                              void* d_out, int out_size) {
    const float* x    = (const float*)d_in[0];
    const float* Wih1 = (const float*)d_in[1];
    const float* Whh1 = (const float*)d_in[2];
    const float* bih1 = (const float*)d_in[3];
    const float* bhh1 = (const float*)d_in[4];
    const float* Wih2 = (const float*)d_in[5];
    const float* Whh2 = (const float*)d_in[6];
    const float* bih2 = (const float*)d_in[7];
    const float* bhh2 = (const float*)d_in[8];
    const float* Wih3 = (const float*)d_in[9];
    const float* Whh3 = (const float*)d_in[10];
    const float* bih3 = (const float*)d_in[11];
    const float* bhh3 = (const float*)d_in[12];
    const float* Wd   = (const float*)d_in[13];
    const float* bd   = (const float*)d_in[14];
    const float* Ww   = (const float*)d_in[15];
    const float* bw   = (const float*)d_in[16];
    const float* Wo   = (const float*)d_in[17];
    const float* bo   = (const float*)d_in[18];
    float* out = (float*)d_out;

    float *xg1, *h1, *xg2, *h2, *xg3, *h3, *WT1, *WT2, *WT3;
    cudaGetSymbolAddress((void**)&xg1, g_xg1);
    cudaGetSymbolAddress((void**)&h1,  g_h1);
    cudaGetSymbolAddress((void**)&xg2, g_xg2);
    cudaGetSymbolAddress((void**)&h2,  g_h2);
    cudaGetSymbolAddress((void**)&xg3, g_xg3);
    cudaGetSymbolAddress((void**)&h3,  g_h3);
    cudaGetSymbolAddress((void**)&WT1, g_WhhT1);
    cudaGetSymbolAddress((void**)&WT2, g_WhhT2);
    cudaGetSymbolAddress((void**)&WT3, g_WhhT3);

    const int M = BB * TT;  // 32768

    // 0) transpose recurrent weights to k-major
    prep_kernel<<<(4 * H1 * H1 + 255) / 256, 256>>>(Whh1, Whh2, Whh3);

    // 1) layer 1: input projection + recurrence
    {
        dim3 grid(M / 128, (4 * H1) / 64);
        gemm_tf32_bias<<<grid, 256>>>(x, Wih1, bih1, bhh1, xg1, M, 4 * H1, DD);
        lstm_kernel<H1, false><<<BB, H1>>>(xg1, WT1, h1);
    }
    // 2) layer 2
    {
        dim3 grid(M / 128, (4 * H2) / 64);
        gemm_tf32_bias<<<grid, 256>>>(h1, Wih2, bih2, bhh2, xg2, M, 4 * H2, H1);
        lstm_kernel<H2, false><<<BB, H2>>>(xg2, WT2, h2);
    }
    // 3) layer 3 (only last hidden state needed)
    {
        dim3 grid(M / 128, (4 * H3) / 64);
        gemm_tf32_bias<<<grid, 256>>>(h2, Wih3, bih3, bhh3, xg3, M, 4 * H3, H2);
        lstm_kernel<H3, true><<<BB, H3>>>(xg3, WT3, h3);
    }
    // 4) head
    head_kernel<<<BB, 32>>>(x, h3, Wd, bd, Ww, bw, Wo, bo, out);

    (void)in_sizes; (void)n_in; (void)out_size;
}

// round 3
// speedup vs baseline: 2.5994x; 2.5994x over previous
#include <cuda_runtime.h>
#include <cstdint>
#include <math.h>

// Problem dims (fixed by the reference)
#define BB 64
#define TT 512
#define DD 2048
#define H1 256
#define H2 128
#define H3 64

// ---------------- scratch (static device buffers; no allocation) ----------------
__device__ float g_xg1[(size_t)BB * TT * 4 * H1];   // 32768 x 1024
__device__ float g_h1 [(size_t)BB * TT * H1];       // 32768 x 256
__device__ float g_xg2[(size_t)BB * TT * 4 * H2];   // 32768 x 512
__device__ float g_h2 [(size_t)BB * TT * H2];       // 32768 x 128
__device__ float g_xg3[(size_t)BB * TT * 4 * H3];   // 32768 x 256
__device__ float g_h3 [(size_t)BB * H3];            // 64 x 64 (last step only)
__device__ float g_hgf[2][(size_t)BB * H1];         // ping-pong h in mma A-fragment layout
__device__ unsigned g_bar[4];                        // grid-barrier counters (per layer)

// ---------------- helpers ----------------
__device__ __forceinline__ float to_tf32(float x) {
    uint32_t u;
    asm("cvt.rna.tf32.f32 %0, %1;" : "=r"(u) : "f"(x));
    return __uint_as_float(u);
}

__device__ __forceinline__ void mma_tf32(float* c, const uint32_t* a, const uint32_t* b) {
    asm volatile(
        "mma.sync.aligned.m16n8k8.row.col.f32.tf32.tf32.f32 "
        "{%0,%1,%2,%3}, {%4,%5,%6,%7}, {%8,%9}, {%0,%1,%2,%3};"
        : "+f"(c[0]), "+f"(c[1]), "+f"(c[2]), "+f"(c[3])
        : "r"(a[0]), "r"(a[1]), "r"(a[2]), "r"(a[3]), "r"(b[0]), "r"(b[1]));
}

__device__ __forceinline__ float sigmoidf_(float x) {
    return 1.0f / (1.0f + expf(-x));
}

// ---------------- prep: zero the grid-barrier counters (every replay) ----------------
__global__ void prep_bar() {
    if (threadIdx.x < 4) g_bar[threadIdx.x] = 0u;
}

// ---------------- tf32 GEMM: C[M,N] = A[M,K] * Bw[N,K]^T + b1[n] + b2[n] ----------------
// BM=128, BN=64, BK=32, 256 threads (8 warps, 4x2 warp grid, 32x32 per warp)
__global__ __launch_bounds__(256) void gemm_tf32_bias(
    const float* __restrict__ A, const float* __restrict__ Bw,
    const float* __restrict__ b1, const float* __restrict__ b2,
    float* __restrict__ C, int M, int N, int K)
{
    constexpr int BM = 128, BN = 64, BK = 32;
    __shared__ float As[BM][BK + 4];
    __shared__ float Bs[BN][BK + 4];

    const int tid  = threadIdx.x;
    const int lane = tid & 31;
    const int warp = tid >> 5;
    const int wm   = warp & 3;   // 0..3
    const int wn   = warp >> 2;  // 0..1
    const int grp  = lane >> 2;  // 0..7
    const int th4  = lane & 3;   // 0..3

    const long bm = (long)blockIdx.x * BM;
    const long bn = (long)blockIdx.y * BN;

    float acc[2][4][4];
#pragma unroll
    for (int i = 0; i < 2; i++)
#pragma unroll
        for (int j = 0; j < 4; j++)
#pragma unroll
            for (int q = 0; q < 4; q++) acc[i][j][q] = 0.0f;

    const int ar = tid >> 3;        // 0..31
    const int ac = (tid & 7) * 4;   // 0..28

    for (int k0 = 0; k0 < K; k0 += BK) {
#pragma unroll
        for (int p = 0; p < 4; ++p) {
            const float4 v = *(const float4*)&A[(bm + ar + p * 32) * (long)K + k0 + ac];
            float4 w;
            w.x = to_tf32(v.x); w.y = to_tf32(v.y); w.z = to_tf32(v.z); w.w = to_tf32(v.w);
            *(float4*)&As[ar + p * 32][ac] = w;
        }
#pragma unroll
        for (int p = 0; p < 2; ++p) {
            const float4 v = *(const float4*)&Bw[(bn + ar + p * 32) * (long)K + k0 + ac];
            float4 w;
            w.x = to_tf32(v.x); w.y = to_tf32(v.y); w.z = to_tf32(v.z); w.w = to_tf32(v.w);
            *(float4*)&Bs[ar + p * 32][ac] = w;
        }
        __syncthreads();

#pragma unroll
        for (int kk = 0; kk < BK; kk += 8) {
            uint32_t afr[2][4];
#pragma unroll
            for (int ms = 0; ms < 2; ++ms) {
                const int mr = wm * 32 + ms * 16 + grp;
                afr[ms][0] = __float_as_uint(As[mr    ][kk + th4    ]);
                afr[ms][1] = __float_as_uint(As[mr + 8][kk + th4    ]);
                afr[ms][2] = __float_as_uint(As[mr    ][kk + th4 + 4]);
                afr[ms][3] = __float_as_uint(As[mr + 8][kk + th4 + 4]);
            }
            uint32_t bfr[4][2];
#pragma unroll
            for (int ns = 0; ns < 4; ++ns) {
                const int nc = wn * 32 + ns * 8 + grp;
                bfr[ns][0] = __float_as_uint(Bs[nc][kk + th4    ]);
                bfr[ns][1] = __float_as_uint(Bs[nc][kk + th4 + 4]);
            }
#pragma unroll
            for (int ms = 0; ms < 2; ++ms)
#pragma unroll
                for (int ns = 0; ns < 4; ++ns)
                    mma_tf32(acc[ms][ns], afr[ms], bfr[ns]);
        }
        __syncthreads();
    }

#pragma unroll
    for (int ms = 0; ms < 2; ++ms) {
#pragma unroll
        for (int ns = 0; ns < 4; ++ns) {
            const long r0 = bm + wm * 32 + ms * 16 + grp;
            const long c0 = bn + wn * 32 + ns * 8 + 2 * th4;
            const float bias0 = b1[c0] + b2[c0];
            const float bias1 = b1[c0 + 1] + b2[c0 + 1];
            C[r0 * N + c0]           = acc[ms][ns][0] + bias0;
            C[r0 * N + c0 + 1]       = acc[ms][ns][1] + bias1;
            C[(r0 + 8) * N + c0]     = acc[ms][ns][2] + bias0;
            C[(r0 + 8) * N + c0 + 1] = acc[ms][ns][3] + bias1;
        }
    }
}

// ---------------- persistent LSTM recurrence (grid-synchronized, tensor-core) ----------------
// H: hidden size, HC: hidden units per CTA. Grid = H/HC CTAs, 256 threads.
// xg: [B,T,4H] precomputed input projection (+ both biases)
// Whh: [4H,H] row-major recurrent weights
// hout: [B,T,H] (or [B,H] when LAST_ONLY)
template <int H, int HC, bool LAST_ONLY>
__global__ __launch_bounds__(256, 1) void lstm_persist(
    const float* __restrict__ xg,
    const float* __restrict__ Whh,
    float* __restrict__ hout,
    unsigned* __restrict__ bar)
{
    constexpr int COLS   = 4 * HC;       // gate columns owned by this CTA
    constexpr int KB     = H / 8;        // k-steps of 8
    constexpr int NT     = COLS / 8;     // n-tiles of 8
    constexpr int NTILES = 4 * NT;       // total (m,n) tiles (M=64 -> 4 m-tiles)
    constexpr int NC     = H / HC;       // number of CTAs
    constexpr int ELEMS  = BB * HC;      // (batch, hidden) elements owned

    __shared__ float Wfrag[NT * KB * 32 * 2];   // B fragments (tf32), float2 per lane
    __shared__ float gS[BB][COLS + 2];          // pre-gate staging

    const int tid  = threadIdx.x;
    const int lane = tid & 31;
    const int w    = tid >> 5;
    const int grp  = lane >> 2;
    const int th4  = lane & 3;
    const int h0   = blockIdx.x * HC;

    // ---- pack Whh slice into SMEM in B-fragment layout (tf32) ----
    for (int fi = tid; fi < NT * KB * 32; fi += 256) {
        const int l   = fi & 31;
        const int kb  = (fi >> 5) % KB;
        const int ni  = (fi >> 5) / KB;
        const int col = ni * 8 + (l >> 2);
        const int k   = kb * 8 + (l & 3);
        const int grow = (col / HC) * H + h0 + (col % HC);
        Wfrag[fi * 2 + 0] = to_tf32(Whh[(size_t)grow * H + k]);
        Wfrag[fi * 2 + 1] = to_tf32(Whh[(size_t)grow * H + k + 4]);
    }
    for (int i = tid; i < BB * (COLS + 2); i += 256)
        ((float*)gS)[i] = 0.0f;

    // ---- elementwise ownership: thread e -> (batch b, hidden jj) ----
    const int b  = tid / HC;
    const int jj = tid % HC;
    const int kme = h0 + jj;            // my hidden index (= k index for next step's A)
    // A-fragment write position for my h value
    const int mi_w   = (b >> 4) & 3;
    const int r_w    = b & 15;
    const int kb_w   = kme >> 3;
    const int kk_w   = kme & 7;
    const int lane_w = (r_w & 7) * 4 + (kk_w & 3);
    const int comp_w = ((kk_w >> 2) << 1) | (r_w >> 3);
    const int fragidx = ((kb_w * 4 + mi_w) * 32 + lane_w) * 4 + comp_w;

    float c = 0.0f;
    float xi = 0.f, xf = 0.f, xgg = 0.f, xo = 0.f;
    if (tid < ELEMS) {
        const float* xp = xg + ((size_t)b * TT) * (4 * H) + kme;
        xi = xp[0]; xf = xp[H]; xgg = xp[2 * H]; xo = xp[3 * H];
    }
    __syncthreads();

    // ---- mma tile assignment ----
    const int  mi = w & 3;
    const int  ni = w >> 2;
    const bool mma_active = (w < NTILES);
    const float2* wf = (const float2*)Wfrag + (size_t)ni * KB * 32 + lane;

    for (int t = 0; t < TT; ++t) {
        if (t > 0 && mma_active) {
            const int rbuf = (t & 1) ^ 1;
            const float4* ha = (const float4*)g_hgf[rbuf];
            float acc[4] = {0.f, 0.f, 0.f, 0.f};
#pragma unroll 8
            for (int kb = 0; kb < KB; ++kb) {
                const float4 a = __ldcg(&ha[(kb * 4 + mi) * 32 + lane]);  // L2-only (cross-CTA)
                const float2 bf = wf[kb * 32];
                uint32_t au[4] = {__float_as_uint(a.x), __float_as_uint(a.y),
                                  __float_as_uint(a.z), __float_as_uint(a.w)};
                uint32_t bu[2] = {__float_as_uint(bf.x), __float_as_uint(bf.y)};
                mma_tf32(acc, au, bu);
            }
            const int rr = mi * 16 + grp;
            const int cc = ni * 8 + 2 * th4;
            gS[rr][cc]         = acc[0];
            gS[rr][cc + 1]     = acc[1];
            gS[rr + 8][cc]     = acc[2];
            gS[rr + 8][cc + 1] = acc[3];
        }
        __syncthreads();

        if (tid < ELEMS) {
            const float pi = gS[b][jj]          + xi;
            const float pf = gS[b][HC + jj]     + xf;
            const float pg = gS[b][2 * HC + jj] + xgg;
            const float po = gS[b][3 * HC + jj] + xo;
            const float iv = sigmoidf_(pi);
            const float fv = sigmoidf_(pf);
            const float gv = tanhf(pg);
            const float ov = sigmoidf_(po);
            c = fv * c + iv * gv;
            const float h = ov * tanhf(c);

            g_hgf[t & 1][fragidx] = to_tf32(h);
            if (!LAST_ONLY) {
                hout[((size_t)b * TT + t) * H + kme] = h;
            } else if (t == TT - 1) {
                hout[(size_t)b * H + kme] = h;
            }
            // prefetch xg for t+1 (latency hidden behind the barrier)
            if (t + 1 < TT) {
                const float* xp = xg + ((size_t)b * TT + (t + 1)) * (4 * H) + kme;
                xi = xp[0]; xf = xp[H]; xgg = xp[2 * H]; xo = xp[3 * H];
            }
        }

        // ---- grid barrier (monotonic counter) ----
        __threadfence();
        __syncthreads();
        if (tid == 0) {
            atomicAdd(bar, 1u);
            const unsigned tgt = (unsigned)NC * (unsigned)(t + 1);
            volatile unsigned* vb = bar;
            while (*vb < tgt) { }
        }
        __syncthreads();
    }
}

// ---------------- head: deep/wide/concat/output ----------------
__global__ void head_kernel(const float* __restrict__ x,
                            const float* __restrict__ h3last,
                            const float* __restrict__ Wd, const float* __restrict__ bd,
                            const float* __restrict__ Ww, const float* __restrict__ bw,
                            const float* __restrict__ Wo, const float* __restrict__ bo,
                            float* __restrict__ out)
{
    const int b = blockIdx.x;
    const int j = threadIdx.x;  // 0..31

    const float* xrow = x + ((size_t)b * TT + (TT - 1)) * DD;
    const float* wwr = Ww + (size_t)j * DD;
    float wide = bw[j];
    for (int k = 0; k < DD; ++k) wide = fmaf(xrow[k], wwr[k], wide);
    wide = fmaxf(wide, 0.0f);

    const float* hrow = h3last + (size_t)b * H3;
    const float* wdr = Wd + (size_t)j * H3;
    float deep = bd[j];
#pragma unroll
    for (int k = 0; k < H3; ++k) deep = fmaf(hrow[k], wdr[k], deep);
    deep = fmaxf(deep, 0.0f);

    float v = deep * Wo[j] + wide * Wo[32 + j];
#pragma unroll
    for (int off = 16; off > 0; off >>= 1)
        v += __shfl_xor_sync(0xffffffffu, v, off);
    if (j == 0) out[b] = v + bo[0];
}

// ---------------- launch ----------------
extern "C" void kernel_launch(void* const* d_in, const int* in_sizes, int n_in,
                              void* d_out, int out_size) {
    const float* x    = (const float*)d_in[0];
    const float* Wih1 = (const float*)d_in[1];
    const float* Whh1 = (const float*)d_in[2];
    const float* bih1 = (const float*)d_in[3];
    const float* bhh1 = (const float*)d_in[4];
    const float* Wih2 = (const float*)d_in[5];
    const float* Whh2 = (const float*)d_in[6];
    const float* bih2 = (const float*)d_in[7];
    const float* bhh2 = (const float*)d_in[8];
    const float* Wih3 = (const float*)d_in[9];
    const float* Whh3 = (const float*)d_in[10];
    const float* bih3 = (const float*)d_in[11];
    const float* bhh3 = (const float*)d_in[12];
    const float* Wd   = (const float*)d_in[13];
    const float* bd   = (const float*)d_in[14];
    const float* Ww   = (const float*)d_in[15];
    const float* bw   = (const float*)d_in[16];
    const float* Wo   = (const float*)d_in[17];
    const float* bo   = (const float*)d_in[18];
    float* out = (float*)d_out;

    float *xg1, *h1, *xg2, *h2, *xg3, *h3;
    unsigned* bar;
    cudaGetSymbolAddress((void**)&xg1, g_xg1);
    cudaGetSymbolAddress((void**)&h1,  g_h1);
    cudaGetSymbolAddress((void**)&xg2, g_xg2);
    cudaGetSymbolAddress((void**)&h2,  g_h2);
    cudaGetSymbolAddress((void**)&xg3, g_xg3);
    cudaGetSymbolAddress((void**)&h3,  g_h3);
    cudaGetSymbolAddress((void**)&bar, g_bar);

    const int M = BB * TT;  // 32768

    prep_bar<<<1, 32>>>();

    // layer 1
    {
        dim3 grid(M / 128, (4 * H1) / 64);
        gemm_tf32_bias<<<grid, 256>>>(x, Wih1, bih1, bhh1, xg1, M, 4 * H1, DD);
        lstm_persist<H1, 4, false><<<H1 / 4, 256>>>(xg1, Whh1, h1, bar + 0);
    }
    // layer 2
    {
        dim3 grid(M / 128, (4 * H2) / 64);
        gemm_tf32_bias<<<grid, 256>>>(h1, Wih2, bih2, bhh2, xg2, M, 4 * H2, H1);
        lstm_persist<H2, 4, false><<<H2 / 4, 256>>>(xg2, Whh2, h2, bar + 1);
    }
    // layer 3 (only last hidden state needed)
    {
        dim3 grid(M / 128, (4 * H3) / 64);
        gemm_tf32_bias<<<grid, 256>>>(h2, Wih3, bih3, bhh3, xg3, M, 4 * H3, H2);
        lstm_persist<H3, 2, true><<<H3 / 2, 256>>>(xg3, Whh3, h3, bar + 2);
    }
    // head
    head_kernel<<<BB, 32>>>(x, h3, Wd, bd, Ww, bw, Wo, bo, out);

    (void)in_sizes; (void)n_in; (void)out_size;
}

// round 4
// speedup vs baseline: 2.7909x; 1.0737x over previous
#include <cuda_runtime.h>
#include <cuda_bf16.h>
#include <cstdint>
#include <math.h>

// Problem dims (fixed by the reference)
#define BB 64
#define TT 512
#define DD 2048
#define H1 256
#define H2 128
#define H3 64

// ---------------- scratch (static device buffers; no allocation) ----------------
__device__ __align__(16) float g_xg1[(size_t)BB * TT * 4 * H1];   // 32768 x 1024
__device__ __align__(16) float g_xg2[(size_t)BB * TT * 4 * H2];   // 32768 x 512
__device__ __align__(16) float g_xg3[(size_t)BB * TT * 4 * H3];   // 32768 x 256
__device__ __align__(16) __nv_bfloat16 g_h1bf[(size_t)BB * TT * H1];  // lstm1 out (bf16)
__device__ __align__(16) __nv_bfloat16 g_h2bf[(size_t)BB * TT * H2];  // lstm2 out (bf16)
__device__ __align__(16) float g_h3[(size_t)BB * H3];                 // lstm3 last h (fp32)
__device__ __align__(16) __nv_bfloat16 g_xbf[(size_t)BB * TT * DD];   // x in bf16
__device__ __align__(16) __nv_bfloat16 g_W1bf[4 * H1 * DD];
__device__ __align__(16) __nv_bfloat16 g_W2bf[4 * H2 * H1];
__device__ __align__(16) __nv_bfloat16 g_W3bf[4 * H3 * H2];
__device__ float g_hgf[2][(size_t)BB * H1];   // ping-pong h in mma A-fragment layout
__device__ unsigned g_bar[4];                 // grid-barrier counters (per layer)

// ---------------- helpers ----------------
__device__ __forceinline__ float to_tf32(float x) {
    uint32_t u;
    asm("cvt.rna.tf32.f32 %0, %1;" : "=r"(u) : "f"(x));
    return __uint_as_float(u);
}

__device__ __forceinline__ void mma_tf32(float* c, const uint32_t* a, const uint32_t* b) {
    asm volatile(
        "mma.sync.aligned.m16n8k8.row.col.f32.tf32.tf32.f32 "
        "{%0,%1,%2,%3}, {%4,%5,%6,%7}, {%8,%9}, {%0,%1,%2,%3};"
        : "+f"(c[0]), "+f"(c[1]), "+f"(c[2]), "+f"(c[3])
        : "r"(a[0]), "r"(a[1]), "r"(a[2]), "r"(a[3]), "r"(b[0]), "r"(b[1]));
}

__device__ __forceinline__ void mma_bf16(float* c, const uint32_t* a, const uint32_t* b) {
    asm volatile(
        "mma.sync.aligned.m16n8k16.row.col.f32.bf16.bf16.f32 "
        "{%0,%1,%2,%3}, {%4,%5,%6,%7}, {%8,%9}, {%0,%1,%2,%3};"
        : "+f"(c[0]), "+f"(c[1]), "+f"(c[2]), "+f"(c[3])
        : "r"(a[0]), "r"(a[1]), "r"(a[2]), "r"(a[3]), "r"(b[0]), "r"(b[1]));
}

__device__ __forceinline__ void ldsm_x4(uint32_t* r, uint32_t addr) {
    asm volatile("ldmatrix.sync.aligned.m8n8.x4.shared.b16 {%0,%1,%2,%3}, [%4];"
                 : "=r"(r[0]), "=r"(r[1]), "=r"(r[2]), "=r"(r[3]) : "r"(addr));
}

__device__ __forceinline__ void cp_async16(uint32_t smem, const void* g) {
    asm volatile("cp.async.cg.shared.global [%0], [%1], 16;" :: "r"(smem), "l"(g));
}

__device__ __forceinline__ float sigmoidf_(float x) {
    return 1.0f / (1.0f + expf(-x));
}

// ---------------- prep: zero the grid-barrier counters (every replay) ----------------
__global__ void prep_bar() {
    if (threadIdx.x < 4) g_bar[threadIdx.x] = 0u;
}

// ---------------- fp32 -> bf16 conversion (vectorized) ----------------
__global__ void f2bf_kernel(const float* __restrict__ src, __nv_bfloat16* __restrict__ dst, int n4) {
    const int stride = gridDim.x * blockDim.x;
    __nv_bfloat162* d2 = (__nv_bfloat162*)dst;
    for (int i = blockIdx.x * blockDim.x + threadIdx.x; i < n4; i += stride) {
        const float4 v = ((const float4*)src)[i];
        d2[2 * i]     = __floats2bfloat162_rn(v.x, v.y);
        d2[2 * i + 1] = __floats2bfloat162_rn(v.z, v.w);
    }
}

// ---------------- bf16 GEMM: C[M,N] = A[M,K] * Bw[N,K]^T + b1[n] + b2[n] ----------------
// BM=128, BN=128, BK=32, 256 threads (8 warps 4x2, warp tile 32x64), cp.async 2-stage
__global__ __launch_bounds__(256, 1) void gemm_bf16_bias(
    const __nv_bfloat16* __restrict__ A, const __nv_bfloat16* __restrict__ Bw,
    const float* __restrict__ b1, const float* __restrict__ b2,
    float* __restrict__ C, int M, int N, int K)
{
    constexpr int BM = 128, BN = 128, BK = 32;
    constexpr int LDA = BK + 8;                    // 40 elems -> 80B row stride (conflict-free ldsm)
    __shared__ __nv_bfloat16 As[2][BM * LDA];
    __shared__ __nv_bfloat16 Bs[2][BN * LDA];

    const int tid  = threadIdx.x;
    const int lane = tid & 31;
    const int warp = tid >> 5;
    const int wm   = warp & 3;   // 0..3
    const int wn   = warp >> 2;  // 0..1

    const long bm = (long)blockIdx.x * BM;
    const long bn = (long)blockIdx.y * BN;

    const uint32_t aBase = (uint32_t)__cvta_generic_to_shared(As);
    const uint32_t bBase = (uint32_t)__cvta_generic_to_shared(Bs);

    // copy mapping: per stage 512 x 16B per operand; 2 per thread each
    const int cr = tid >> 2;            // 0..63 (+64 on second op)
    const int cs = (tid & 3) * 8;       // 0,8,16,24 (elems)

    auto issue = [&](int st, int k0) {
#pragma unroll
        for (int i = 0; i < 2; ++i) {
            const int r = cr + i * 64;
            cp_async16(aBase + (uint32_t)(st * BM * LDA + r * LDA + cs) * 2,
                       A + (size_t)(bm + r) * K + k0 + cs);
            cp_async16(bBase + (uint32_t)(st * BN * LDA + r * LDA + cs) * 2,
                       Bw + (size_t)(bn + r) * K + k0 + cs);
        }
    };

    const int KT = K / BK;

    issue(0, 0);
    asm volatile("cp.async.commit_group;");
    issue(1, BK);
    asm volatile("cp.async.commit_group;");

    float acc[2][8][4];
#pragma unroll
    for (int mf = 0; mf < 2; ++mf)
#pragma unroll
        for (int nt = 0; nt < 8; ++nt)
#pragma unroll
            for (int q = 0; q < 4; ++q) acc[mf][nt][q] = 0.0f;

    // ldmatrix lane-invariant address pieces
    const int aRow = wm * 32 + (lane & 15);
    const int aColH = (lane >> 4) << 3;            // 0 or 8
    const int bRow = wn * 64 + (((lane >> 4) & 1) << 3) + (lane & 7);
    const int bColH = ((lane >> 3) & 1) << 3;      // 0 or 8

    for (int kt = 0; kt < KT; ++kt) {
        asm volatile("cp.async.wait_group 1;");
        __syncthreads();
        const int st = kt & 1;
        const uint32_t aS = aBase + (uint32_t)(st * BM * LDA) * 2;
        const uint32_t bS = bBase + (uint32_t)(st * BN * LDA) * 2;

#pragma unroll
        for (int kf = 0; kf < 2; ++kf) {
            const int k0 = kf * 16;
            uint32_t afr[2][4];
#pragma unroll
            for (int mf = 0; mf < 2; ++mf)
                ldsm_x4(afr[mf], aS + (uint32_t)((aRow + mf * 16) * LDA + k0 + aColH) * 2);
            uint32_t bfr[4][4];
#pragma unroll
            for (int np = 0; np < 4; ++np)
                ldsm_x4(bfr[np], bS + (uint32_t)((bRow + np * 16) * LDA + k0 + bColH) * 2);
#pragma unroll
            for (int mf = 0; mf < 2; ++mf)
#pragma unroll
                for (int nt = 0; nt < 8; ++nt)
                    mma_bf16(acc[mf][nt], afr[mf], &bfr[nt >> 1][(nt & 1) * 2]);
        }
        __syncthreads();
        if (kt + 2 < KT) issue(st, (kt + 2) * BK);
        asm volatile("cp.async.commit_group;");
    }

    // epilogue with bias
#pragma unroll
    for (int mf = 0; mf < 2; ++mf) {
#pragma unroll
        for (int nt = 0; nt < 8; ++nt) {
            const long r0 = bm + wm * 32 + mf * 16 + (lane >> 2);
            const long c0 = bn + wn * 64 + nt * 8 + 2 * (lane & 3);
            const float bias0 = b1[c0] + b2[c0];
            const float bias1 = b1[c0 + 1] + b2[c0 + 1];
            C[r0 * N + c0]           = acc[mf][nt][0] + bias0;
            C[r0 * N + c0 + 1]       = acc[mf][nt][1] + bias1;
            C[(r0 + 8) * N + c0]     = acc[mf][nt][2] + bias0;
            C[(r0 + 8) * N + c0 + 1] = acc[mf][nt][3] + bias1;
        }
    }
}

// ---------------- persistent LSTM recurrence (grid-synchronized, tensor-core) ----------------
// 512 threads, 16 mma warps. NTILES*SPLITK must equal 16.
template <int H, int HC, int SPLITK, bool LAST_ONLY>
__global__ __launch_bounds__(512, 1) void lstm_persist(
    const float* __restrict__ xg,
    const float* __restrict__ Whh,
    void* __restrict__ hout_v,
    unsigned* __restrict__ bar)
{
    constexpr int COLS   = 4 * HC;
    constexpr int KB     = H / 8;
    constexpr int NT     = COLS / 8;
    constexpr int NTILES = 4 * NT;
    constexpr int KS     = KB / SPLITK;
    constexpr int NC     = H / HC;
    constexpr int ELEMS  = BB * HC;
    static_assert(NTILES * SPLITK == 16, "warp mapping");
    static_assert((KS & 1) == 0, "dual acc chains need even KS");

    __shared__ float2 Wfrag[NT * KB * 32];
    __shared__ float gS[SPLITK][BB][COLS + 2];

    const int tid  = threadIdx.x;
    const int lane = tid & 31;
    const int w    = tid >> 5;
    const int grp  = lane >> 2;
    const int th4  = lane & 3;
    const int h0   = blockIdx.x * HC;

    // ---- pack Whh slice into SMEM in tf32 B-fragment layout ----
    for (int fi = tid; fi < NT * KB * 32; fi += 512) {
        const int l   = fi & 31;
        const int kb  = (fi >> 5) % KB;
        const int ni  = (fi >> 5) / KB;
        const int col = ni * 8 + (l >> 2);
        const int k   = kb * 8 + (l & 3);
        const int grow = (col / HC) * H + h0 + (col % HC);
        Wfrag[fi] = make_float2(to_tf32(Whh[(size_t)grow * H + k]),
                                to_tf32(Whh[(size_t)grow * H + k + 4]));
    }
    for (int i = tid; i < SPLITK * BB * (COLS + 2); i += 512)
        ((float*)gS)[i] = 0.0f;

    // ---- elementwise ownership ----
    const bool ew = (tid < ELEMS);
    const int b  = tid / HC;
    const int jj = tid % HC;
    const int kme = h0 + jj;
    const int mi_w   = (b >> 4) & 3;
    const int r_w    = b & 15;
    const int kb_w   = kme >> 3;
    const int kk_w   = kme & 7;
    const int lane_w = (r_w & 7) * 4 + (kk_w & 3);
    const int comp_w = ((kk_w >> 2) << 1) | (r_w >> 3);
    const int fragidx = ((kb_w * 4 + mi_w) * 32 + lane_w) * 4 + comp_w;

    float c = 0.0f;
    float xi = 0.f, xf = 0.f, xgg = 0.f, xo = 0.f;
    if (ew) {
        const float* xp = xg + ((size_t)b * TT) * (4 * H) + kme;
        xi = xp[0]; xf = xp[H]; xgg = xp[2 * H]; xo = xp[3 * H];
    }
    __syncthreads();

    // ---- mma tile assignment (16 warps) ----
    const int tile = w & (NTILES - 1);
    const int half = w / NTILES;       // 0 (or 0/1 when SPLITK=2)
    const int mi   = tile & 3;
    const int ni   = tile >> 2;
    const int klo  = half * KS;
    const float2* wf = (const float2*)Wfrag + (size_t)ni * KB * 32 + lane;

    for (int t = 0; t < TT; ++t) {
        if (t > 0) {
            const int rbuf = (t & 1) ^ 1;
            const float4* ha = (const float4*)g_hgf[rbuf];
            float a0[4] = {0.f, 0.f, 0.f, 0.f};
            float a1[4] = {0.f, 0.f, 0.f, 0.f};
#pragma unroll 4
            for (int kb = klo; kb < klo + KS; kb += 2) {
                const float4 av0 = __ldcg(&ha[(kb * 4 + mi) * 32 + lane]);
                const float4 av1 = __ldcg(&ha[((kb + 1) * 4 + mi) * 32 + lane]);
                const float2 bf0 = wf[kb * 32];
                const float2 bf1 = wf[(kb + 1) * 32];
                uint32_t au0[4] = {__float_as_uint(av0.x), __float_as_uint(av0.y),
                                   __float_as_uint(av0.z), __float_as_uint(av0.w)};
                uint32_t bu0[2] = {__float_as_uint(bf0.x), __float_as_uint(bf0.y)};
                mma_tf32(a0, au0, bu0);
                uint32_t au1[4] = {__float_as_uint(av1.x), __float_as_uint(av1.y),
                                   __float_as_uint(av1.z), __float_as_uint(av1.w)};
                uint32_t bu1[2] = {__float_as_uint(bf1.x), __float_as_uint(bf1.y)};
                mma_tf32(a1, au1, bu1);
            }
            const int rr = mi * 16 + grp;
            const int cc = ni * 8 + 2 * th4;
            gS[half][rr][cc]         = a0[0] + a1[0];
            gS[half][rr][cc + 1]     = a0[1] + a1[1];
            gS[half][rr + 8][cc]     = a0[2] + a1[2];
            gS[half][rr + 8][cc + 1] = a0[3] + a1[3];
        }
        __syncthreads();

        if (ew) {
            float pi = gS[0][b][jj]          + xi;
            float pf = gS[0][b][HC + jj]     + xf;
            float pg = gS[0][b][2 * HC + jj] + xgg;
            float po = gS[0][b][3 * HC + jj] + xo;
            if (SPLITK == 2) {
                pi += gS[1][b][jj];
                pf += gS[1][b][HC + jj];
                pg += gS[1][b][2 * HC + jj];
                po += gS[1][b][3 * HC + jj];
            }
            const float iv = sigmoidf_(pi);
            const float fv = sigmoidf_(pf);
            const float gv = tanhf(pg);
            const float ov = sigmoidf_(po);
            c = fv * c + iv * gv;
            const float h = ov * tanhf(c);

            g_hgf[t & 1][fragidx] = to_tf32(h);
            if (!LAST_ONLY) {
                ((__nv_bfloat16*)hout_v)[((size_t)b * TT + t) * H + kme] = __float2bfloat16(h);
            } else if (t == TT - 1) {
                ((float*)hout_v)[(size_t)b * H + kme] = h;
            }
            if (t + 1 < TT) {
                const float* xp = xg + ((size_t)b * TT + (t + 1)) * (4 * H) + kme;
                xi = xp[0]; xf = xp[H]; xgg = xp[2 * H]; xo = xp[3 * H];
            }
        }

        // ---- grid barrier: release-add + acquire-poll (no membar.gl) ----
        __syncthreads();
        if (tid == 0) {
            asm volatile("red.release.gpu.global.add.u32 [%0], 1;" :: "l"(bar) : "memory");
            const unsigned tgt = (unsigned)NC * (unsigned)(t + 1);
            unsigned v;
            do {
                asm volatile("ld.acquire.gpu.global.u32 %0, [%1];" : "=r"(v) : "l"(bar) : "memory");
            } while (v < tgt);
        }
        __syncthreads();
    }
}

// ---------------- head: deep/wide/concat/output (256 threads) ----------------
__global__ __launch_bounds__(256) void head_kernel(
    const float* __restrict__ x,
    const float* __restrict__ h3last,
    const float* __restrict__ Wd, const float* __restrict__ bd,
    const float* __restrict__ Ww, const float* __restrict__ bw,
    const float* __restrict__ Wo, const float* __restrict__ bo,
    float* __restrict__ out)
{
    const int bidx = blockIdx.x;
    const int j = threadIdx.x & 31;   // output unit
    const int s = threadIdx.x >> 5;   // k-slice (8 warps)
    __shared__ float red[8][33];

    const float* xrow = x + ((size_t)bidx * TT + (TT - 1)) * DD;
    const float* wwr = Ww + (size_t)j * DD;
    float acc = 0.0f;
    const int k0 = s * (DD / 8);
#pragma unroll 4
    for (int k = k0; k < k0 + DD / 8; k += 4) {
        const float4 xv = *(const float4*)&xrow[k];
        const float4 wv = *(const float4*)&wwr[k];
        acc = fmaf(xv.x, wv.x, acc);
        acc = fmaf(xv.y, wv.y, acc);
        acc = fmaf(xv.z, wv.z, acc);
        acc = fmaf(xv.w, wv.w, acc);
    }
    red[s][j] = acc;
    __syncthreads();

    if (s == 0) {
        float wide = bw[j];
#pragma unroll
        for (int q = 0; q < 8; ++q) wide += red[q][j];
        wide = fmaxf(wide, 0.0f);

        const float* hrow = h3last + (size_t)bidx * H3;
        const float* wdr = Wd + (size_t)j * H3;
        float deep = bd[j];
#pragma unroll
        for (int k = 0; k < H3; ++k) deep = fmaf(hrow[k], wdr[k], deep);
        deep = fmaxf(deep, 0.0f);

        float v = deep * Wo[j] + wide * Wo[32 + j];
#pragma unroll
        for (int off = 16; off > 0; off >>= 1)
            v += __shfl_xor_sync(0xffffffffu, v, off);
        if (j == 0) out[bidx] = v + bo[0];
    }
}

// ---------------- launch ----------------
extern "C" void kernel_launch(void* const* d_in, const int* in_sizes, int n_in,
                              void* d_out, int out_size) {
    const float* x    = (const float*)d_in[0];
    const float* Wih1 = (const float*)d_in[1];
    const float* Whh1 = (const float*)d_in[2];
    const float* bih1 = (const float*)d_in[3];
    const float* bhh1 = (const float*)d_in[4];
    const float* Wih2 = (const float*)d_in[5];
    const float* Whh2 = (const float*)d_in[6];
    const float* bih2 = (const float*)d_in[7];
    const float* bhh2 = (const float*)d_in[8];
    const float* Wih3 = (const float*)d_in[9];
    const float* Whh3 = (const float*)d_in[10];
    const float* bih3 = (const float*)d_in[11];
    const float* bhh3 = (const float*)d_in[12];
    const float* Wd   = (const float*)d_in[13];
    const float* bd   = (const float*)d_in[14];
    const float* Ww   = (const float*)d_in[15];
    const float* bw   = (const float*)d_in[16];
    const float* Wo   = (const float*)d_in[17];
    const float* bo   = (const float*)d_in[18];
    float* out = (float*)d_out;

    float *xg1, *xg2, *xg3, *h3;
    __nv_bfloat16 *h1bf, *h2bf, *xbf, *W1bf, *W2bf, *W3bf;
    unsigned* bar;
    cudaGetSymbolAddress((void**)&xg1,  g_xg1);
    cudaGetSymbolAddress((void**)&xg2,  g_xg2);
    cudaGetSymbolAddress((void**)&xg3,  g_xg3);
    cudaGetSymbolAddress((void**)&h1bf, g_h1bf);
    cudaGetSymbolAddress((void**)&h2bf, g_h2bf);
    cudaGetSymbolAddress((void**)&h3,   g_h3);
    cudaGetSymbolAddress((void**)&xbf,  g_xbf);
    cudaGetSymbolAddress((void**)&W1bf, g_W1bf);
    cudaGetSymbolAddress((void**)&W2bf, g_W2bf);
    cudaGetSymbolAddress((void**)&W3bf, g_W3bf);
    cudaGetSymbolAddress((void**)&bar,  g_bar);

    const int M = BB * TT;  // 32768

    prep_bar<<<1, 32>>>();

    // convert inputs/weights to bf16
    f2bf_kernel<<<4096, 256>>>(x,    xbf,  (BB * TT * DD) / 4);
    f2bf_kernel<<<512,  256>>>(Wih1, W1bf, (4 * H1 * DD) / 4);
    f2bf_kernel<<<64,   256>>>(Wih2, W2bf, (4 * H2 * H1) / 4);
    f2bf_kernel<<<16,   256>>>(Wih3, W3bf, (4 * H3 * H2) / 4);

    // layer 1
    {
        dim3 grid(M / 128, (4 * H1) / 128);
        gemm_bf16_bias<<<grid, 256>>>(xbf, W1bf, bih1, bhh1, xg1, M, 4 * H1, DD);
        lstm_persist<H1, 8, 1, false><<<H1 / 8, 512>>>(xg1, Whh1, h1bf, bar + 0);
    }
    // layer 2
    {
        dim3 grid(M / 128, (4 * H2) / 128);
        gemm_bf16_bias<<<grid, 256>>>(h1bf, W2bf, bih2, bhh2, xg2, M, 4 * H2, H1);
        lstm_persist<H2, 8, 1, false><<<H2 / 8, 512>>>(xg2, Whh2, h2bf, bar + 1);
    }
    // layer 3 (only last hidden state needed)
    {
        dim3 grid(M / 128, (4 * H3) / 128);
        gemm_bf16_bias<<<grid, 256>>>(h2bf, W3bf, bih3, bhh3, xg3, M, 4 * H3, H2);
        lstm_persist<H3, 4, 2, true><<<H3 / 4, 512>>>(xg3, Whh3, h3, bar + 2);
    }
    // head
    head_kernel<<<BB, 256>>>(x, h3, Wd, bd, Ww, bw, Wo, bo, out);

    (void)in_sizes; (void)n_in; (void)out_size;
}

// round 5
// speedup vs baseline: 4.9972x; 1.7905x over previous
#include <cuda_runtime.h>
#include <cuda_bf16.h>
#include <cstdint>
#include <math.h>

// Problem dims (fixed by the reference)
#define BB 64
#define TT 512
#define DD 2048
#define H1C 256
#define H2C 128
#define H3C 64

#define NCTA_L1 32
#define NCTA_L2 16
#define NCTA_L3 8
#define NCTA_ALL 56
#define TOTS (TT + 2)

// ---------------- scratch (static device buffers; no allocation) ----------------
__device__ __align__(16) float g_xg1[(size_t)BB * TT * 4 * H1C];   // 32768 x 1024
__device__ __align__(16) __nv_bfloat16 g_xbf[(size_t)BB * TT * DD];
__device__ __align__(16) __nv_bfloat16 g_W1bf[4 * H1C * DD];
__device__ __align__(16) float g_hf1[2][BB * H1C];   // h1 ping-pong, mma A-fragment layout
__device__ __align__(16) float g_hf2[2][BB * H2C];
__device__ __align__(16) float g_hf3[2][BB * H3C];
__device__ __align__(16) float g_h3[BB * H3C];       // layer-3 last h (fp32)
__device__ unsigned g_flags[NCTA_ALL * 32];          // one flag per CTA, 128B apart

// ---------------- helpers ----------------
__device__ __forceinline__ float to_tf32(float x) {
    uint32_t u;
    asm("cvt.rna.tf32.f32 %0, %1;" : "=r"(u) : "f"(x));
    return __uint_as_float(u);
}

__device__ __forceinline__ void mma_tf32(float* c, const uint32_t* a, const uint32_t* b) {
    asm volatile(
        "mma.sync.aligned.m16n8k8.row.col.f32.tf32.tf32.f32 "
        "{%0,%1,%2,%3}, {%4,%5,%6,%7}, {%8,%9}, {%0,%1,%2,%3};"
        : "+f"(c[0]), "+f"(c[1]), "+f"(c[2]), "+f"(c[3])
        : "r"(a[0]), "r"(a[1]), "r"(a[2]), "r"(a[3]), "r"(b[0]), "r"(b[1]));
}

__device__ __forceinline__ void mma_bf16(float* c, const uint32_t* a, const uint32_t* b) {
    asm volatile(
        "mma.sync.aligned.m16n8k16.row.col.f32.bf16.bf16.f32 "
        "{%0,%1,%2,%3}, {%4,%5,%6,%7}, {%8,%9}, {%0,%1,%2,%3};"
        : "+f"(c[0]), "+f"(c[1]), "+f"(c[2]), "+f"(c[3])
        : "r"(a[0]), "r"(a[1]), "r"(a[2]), "r"(a[3]), "r"(b[0]), "r"(b[1]));
}

__device__ __forceinline__ void ldsm_x4(uint32_t* r, uint32_t addr) {
    asm volatile("ldmatrix.sync.aligned.m8n8.x4.shared.b16 {%0,%1,%2,%3}, [%4];"
                 : "=r"(r[0]), "=r"(r[1]), "=r"(r[2]), "=r"(r[3]) : "r"(addr));
}

__device__ __forceinline__ void cp_async16(uint32_t smem, const void* g) {
    asm volatile("cp.async.cg.shared.global [%0], [%1], 16;" :: "r"(smem), "l"(g));
}

__device__ __forceinline__ float rcp_(float x) {
    float r;
    asm("rcp.approx.f32 %0, %1;" : "=f"(r) : "f"(x));
    return r;
}
__device__ __forceinline__ float fast_sig(float x) {
    return rcp_(1.0f + __expf(-x));
}
__device__ __forceinline__ float fast_tanh(float x) {
    return 2.0f * rcp_(1.0f + __expf(-2.0f * x)) - 1.0f;
}

// ---------------- prep: zero the barrier flags (every replay) ----------------
__global__ void prep_flags() {
    const int i = blockIdx.x * blockDim.x + threadIdx.x;
    if (i < NCTA_ALL * 32) g_flags[i] = 0u;
}

// ---------------- fp32 -> bf16 conversion (vectorized) ----------------
__global__ void f2bf_kernel(const float* __restrict__ src, __nv_bfloat16* __restrict__ dst, int n4) {
    const int stride = gridDim.x * blockDim.x;
    __nv_bfloat162* d2 = (__nv_bfloat162*)dst;
    for (int i = blockIdx.x * blockDim.x + threadIdx.x; i < n4; i += stride) {
        const float4 v = ((const float4*)src)[i];
        d2[2 * i]     = __floats2bfloat162_rn(v.x, v.y);
        d2[2 * i + 1] = __floats2bfloat162_rn(v.z, v.w);
    }
}

// ---------------- bf16 GEMM: C[M,N] = A[M,K] * Bw[N,K]^T + b1[n] + b2[n] ----------------
// BM=128, BN=128, BK=32, 256 threads; grid.x = N tiles (fast) for A-tile L2 reuse.
__global__ __launch_bounds__(256, 1) void gemm_bf16_bias(
    const __nv_bfloat16* __restrict__ A, const __nv_bfloat16* __restrict__ Bw,
    const float* __restrict__ b1, const float* __restrict__ b2,
    float* __restrict__ C, int M, int N, int K)
{
    constexpr int BM = 128, BN = 128, BK = 32;
    constexpr int LDA = BK + 8;
    __shared__ __nv_bfloat16 As[2][BM * LDA];
    __shared__ __nv_bfloat16 Bs[2][BN * LDA];

    const int tid  = threadIdx.x;
    const int lane = tid & 31;
    const int warp = tid >> 5;
    const int wm   = warp & 3;
    const int wn   = warp >> 2;

    const long bm = (long)blockIdx.y * BM;   // M tile (slow dim)
    const long bn = (long)blockIdx.x * BN;   // N tile (fast dim)

    const uint32_t aBase = (uint32_t)__cvta_generic_to_shared(As);
    const uint32_t bBase = (uint32_t)__cvta_generic_to_shared(Bs);

    const int cr = tid >> 2;
    const int cs = (tid & 3) * 8;

    auto issue = [&](int st, int k0) {
#pragma unroll
        for (int i = 0; i < 2; ++i) {
            const int r = cr + i * 64;
            cp_async16(aBase + (uint32_t)(st * BM * LDA + r * LDA + cs) * 2,
                       A + (size_t)(bm + r) * K + k0 + cs);
            cp_async16(bBase + (uint32_t)(st * BN * LDA + r * LDA + cs) * 2,
                       Bw + (size_t)(bn + r) * K + k0 + cs);
        }
    };

    const int KT = K / BK;

    issue(0, 0);
    asm volatile("cp.async.commit_group;");
    issue(1, BK);
    asm volatile("cp.async.commit_group;");

    float acc[2][8][4];
#pragma unroll
    for (int mf = 0; mf < 2; ++mf)
#pragma unroll
        for (int nt = 0; nt < 8; ++nt)
#pragma unroll
            for (int q = 0; q < 4; ++q) acc[mf][nt][q] = 0.0f;

    const int aRow = wm * 32 + (lane & 15);
    const int aColH = (lane >> 4) << 3;
    const int bRow = wn * 64 + (((lane >> 4) & 1) << 3) + (lane & 7);
    const int bColH = ((lane >> 3) & 1) << 3;

    for (int kt = 0; kt < KT; ++kt) {
        asm volatile("cp.async.wait_group 1;");
        __syncthreads();
        const int st = kt & 1;
        const uint32_t aS = aBase + (uint32_t)(st * BM * LDA) * 2;
        const uint32_t bS = bBase + (uint32_t)(st * BN * LDA) * 2;

#pragma unroll
        for (int kf = 0; kf < 2; ++kf) {
            const int k0 = kf * 16;
            uint32_t afr[2][4];
#pragma unroll
            for (int mf = 0; mf < 2; ++mf)
                ldsm_x4(afr[mf], aS + (uint32_t)((aRow + mf * 16) * LDA + k0 + aColH) * 2);
            uint32_t bfr[4][4];
#pragma unroll
            for (int np = 0; np < 4; ++np)
                ldsm_x4(bfr[np], bS + (uint32_t)((bRow + np * 16) * LDA + k0 + bColH) * 2);
#pragma unroll
            for (int mf = 0; mf < 2; ++mf)
#pragma unroll
                for (int nt = 0; nt < 8; ++nt)
                    mma_bf16(acc[mf][nt], afr[mf], &bfr[nt >> 1][(nt & 1) * 2]);
        }
        __syncthreads();
        if (kt + 2 < KT) issue(st, (kt + 2) * BK);
        asm volatile("cp.async.commit_group;");
    }

#pragma unroll
    for (int mf = 0; mf < 2; ++mf) {
#pragma unroll
        for (int nt = 0; nt < 8; ++nt) {
            const long r0 = bm + wm * 32 + mf * 16 + (lane >> 2);
            const long c0 = bn + wn * 64 + nt * 8 + 2 * (lane & 3);
            const float bias0 = b1[c0] + b2[c0];
            const float bias1 = b1[c0 + 1] + b2[c0 + 1];
            C[r0 * N + c0]           = acc[mf][nt][0] + bias0;
            C[r0 * N + c0 + 1]       = acc[mf][nt][1] + bias1;
            C[(r0 + 8) * N + c0]     = acc[mf][nt][2] + bias0;
            C[(r0 + 8) * N + c0 + 1] = acc[mf][nt][3] + bias1;
        }
    }
}

// ---------------- fused 3-layer pipelined LSTM (one barrier per global step) ----------------
// Role: H hidden, KP proj input size (0 => xg precomputed in gmem), HC=8 units/CTA,
// FIRST = pipeline offset, LAST_ONLY => only final h written (to hlast).
template <int H, int KP, int FIRST, bool LAST_ONLY>
__device__ __forceinline__ void lstm_role(
    float* dyn,
    const float* __restrict__ xg,
    const float* __restrict__ Wih,
    const float* __restrict__ Whh,
    const float* __restrict__ bih,
    const float* __restrict__ bhh,
    const float* __restrict__ hfp0, const float* __restrict__ hfp1,
    float* __restrict__ hfo0, float* __restrict__ hfo1,
    float* __restrict__ hlast,
    unsigned* __restrict__ flags,
    int ctaLocal, int myflag)
{
    constexpr int HC   = 8;
    constexpr int COLS = 4 * HC;        // 32
    constexpr int GSW  = COLS + 2;      // 34
    constexpr int NT   = COLS / 8;      // 4
    constexpr int KBR  = H / 8;
    constexpr int KBP  = (KP > 0) ? KP / 8 : 0;

    float2* WR = (float2*)dyn;
    float2* WP = WR + NT * KBR * 32;
    float*  gS = (float*)(WP + NT * KBP * 32);
    float*  hS = gS + BB * GSW;

    const int tid  = threadIdx.x;
    const int lane = tid & 31;
    const int w    = tid >> 5;
    const int grp  = lane >> 2;
    const int th4  = lane & 3;
    const int h0   = ctaLocal * HC;

    // ---- pack recurrent weights into tf32 B-fragment layout ----
    for (int fi = tid; fi < NT * KBR * 32; fi += 512) {
        const int l   = fi & 31;
        const int kb  = (fi >> 5) % KBR;
        const int ni  = (fi >> 5) / KBR;
        const int col = ni * 8 + (l >> 2);
        const int k   = kb * 8 + (l & 3);
        const int grow = (col / HC) * H + h0 + (col % HC);
        WR[fi] = make_float2(to_tf32(Whh[(size_t)grow * H + k]),
                             to_tf32(Whh[(size_t)grow * H + k + 4]));
    }
    if (KP > 0) {
        for (int fi = tid; fi < NT * KBP * 32; fi += 512) {
            const int l   = fi & 31;
            const int kb  = (fi >> 5) % KBP;
            const int ni  = (fi >> 5) / KBP;
            const int col = ni * 8 + (l >> 2);
            const int k   = kb * 8 + (l & 3);
            const int grow = (col / HC) * H + h0 + (col % HC);
            WP[fi] = make_float2(to_tf32(Wih[(size_t)grow * KP + k]),
                                 to_tf32(Wih[(size_t)grow * KP + k + 4]));
        }
    }
    for (int i = tid; i < BB * GSW; i += 512) gS[i] = 0.0f;

    // ---- elementwise ownership: thread -> (batch b, unit jj) ----
    const int b  = tid >> 3;           // 0..63
    const int jj = tid & 7;            // 0..7
    const int kme = h0 + jj;
    // local fragment index within this CTA's kb block
    const int r_w    = b & 15;
    const int mi_w   = b >> 4;
    const int lane_w = (r_w & 7) * 4 + (jj & 3);
    const int comp_w = ((jj >> 2) << 1) | (r_w >> 3);
    const int lf = (mi_w * 32 + lane_w) * 4 + comp_w;

    float c = 0.0f;
    float xi = 0.f, xf = 0.f, xgv = 0.f, xo = 0.f;
    if (KP == 0) {
        const float* xp = xg + ((size_t)b * TT) * (4 * H) + kme;
        xi = xp[0]; xf = xp[H]; xgv = xp[2 * H]; xo = xp[3 * H];
    } else {
        xi  = bih[kme]         + bhh[kme];
        xf  = bih[H + kme]     + bhh[H + kme];
        xgv = bih[2 * H + kme] + bhh[2 * H + kme];
        xo  = bih[3 * H + kme] + bhh[3 * H + kme];
    }
    __syncthreads();

    // ---- warp tile (16 warps = 4 m x 4 n tiles) ----
    const int mi = w & 3;
    const int ni = w >> 2;
    const float2* wpB = WP + (size_t)ni * KBP * 32 + lane;
    const float2* wrB = WR + (size_t)ni * KBR * 32 + lane;

    for (int s = 0; s < TOTS; ++s) {
        const int t = s - FIRST;
        const bool active = (t >= 0) && (t < TT);

        if (active) {
            float A0[4] = {0.f,0.f,0.f,0.f}, A1[4] = {0.f,0.f,0.f,0.f};
            float A2[4] = {0.f,0.f,0.f,0.f}, A3[4] = {0.f,0.f,0.f,0.f};
            bool didmma = false;
            if (KP > 0) {
                didmma = true;
                const float4* hp = (const float4*)((t & 1) ? hfp1 : hfp0);
#pragma unroll
                for (int kb = 0; kb < KBP; kb += 4) {
#pragma unroll
                    for (int q = 0; q < 4; ++q) {
                        const float4 a = __ldcg(&hp[((kb + q) * 4 + mi) * 32 + lane]);
                        const float2 bw = wpB[(kb + q) * 32];
                        uint32_t au[4] = {__float_as_uint(a.x), __float_as_uint(a.y),
                                          __float_as_uint(a.z), __float_as_uint(a.w)};
                        uint32_t bu[2] = {__float_as_uint(bw.x), __float_as_uint(bw.y)};
                        mma_tf32(q == 0 ? A0 : (q == 1 ? A1 : (q == 2 ? A2 : A3)), au, bu);
                    }
                }
            }
            if (t > 0) {
                didmma = true;
                const float4* hr = (const float4*)((t & 1) ? hfo0 : hfo1);
#pragma unroll
                for (int kb = 0; kb < KBR; kb += 4) {
#pragma unroll
                    for (int q = 0; q < 4; ++q) {
                        const float4 a = __ldcg(&hr[((kb + q) * 4 + mi) * 32 + lane]);
                        const float2 bw = wrB[(kb + q) * 32];
                        uint32_t au[4] = {__float_as_uint(a.x), __float_as_uint(a.y),
                                          __float_as_uint(a.z), __float_as_uint(a.w)};
                        uint32_t bu[2] = {__float_as_uint(bw.x), __float_as_uint(bw.y)};
                        mma_tf32(q == 0 ? A0 : (q == 1 ? A1 : (q == 2 ? A2 : A3)), au, bu);
                    }
                }
            }
            if (didmma) {
                const int rr = mi * 16 + grp;
                const int cc = ni * 8 + 2 * th4;
                gS[rr * GSW + cc]           = A0[0] + A1[0] + A2[0] + A3[0];
                gS[rr * GSW + cc + 1]       = A0[1] + A1[1] + A2[1] + A3[1];
                gS[(rr + 8) * GSW + cc]     = A0[2] + A1[2] + A2[2] + A3[2];
                gS[(rr + 8) * GSW + cc + 1] = A0[3] + A1[3] + A2[3] + A3[3];
            }
        }
        __syncthreads();

        if (active) {
            const float pi = gS[b * GSW + jj]          + xi;
            const float pf = gS[b * GSW + HC + jj]     + xf;
            const float pg = gS[b * GSW + 2 * HC + jj] + xgv;
            const float po = gS[b * GSW + 3 * HC + jj] + xo;
            const float iv = fast_sig(pi);
            const float fv = fast_sig(pf);
            const float gv = fast_tanh(pg);
            const float ov = fast_sig(po);
            c = fv * c + iv * gv;
            const float h = ov * fast_tanh(c);
            hS[lf] = to_tf32(h);

            if (LAST_ONLY && t == TT - 1)
                hlast[(size_t)b * H + kme] = h;

            if (KP == 0 && t + 1 < TT) {
                const float* xp = xg + ((size_t)b * TT + (t + 1)) * (4 * H) + kme;
                xi = xp[0]; xf = xp[H]; xgv = xp[2 * H]; xo = xp[3 * H];
            }
        }
        __syncthreads();

        // coalesced fragment store (2KB per CTA)
        if (active && tid < 128) {
            float4* wdst = (float4*)((t & 1) ? hfo1 : hfo0) + h0 * 16 + tid;
            *wdst = ((const float4*)hS)[tid];
        }
        __syncthreads();

        // ---- distributed flag barrier ----
        if (tid == 0) {
            asm volatile("st.release.gpu.global.u32 [%0], %1;"
                         :: "l"(flags + myflag * 32), "r"((unsigned)(s + 1)) : "memory");
        }
        if (tid < NCTA_ALL) {
            unsigned v;
            const unsigned tgt = (unsigned)(s + 1);
            unsigned* fp = flags + tid * 32;
            do {
                asm volatile("ld.acquire.gpu.global.u32 %0, [%1];" : "=r"(v) : "l"(fp) : "memory");
            } while (v < tgt);
        }
        __syncthreads();
    }
}

__global__ __launch_bounds__(512, 1) void lstm_fused(
    const float* __restrict__ xg1,
    const float* __restrict__ Whh1,
    const float* __restrict__ Wih2, const float* __restrict__ Whh2,
    const float* __restrict__ bih2, const float* __restrict__ bhh2,
    const float* __restrict__ Wih3, const float* __restrict__ Whh3,
    const float* __restrict__ bih3, const float* __restrict__ bhh3,
    float* __restrict__ h3out, unsigned* __restrict__ flags)
{
    extern __shared__ float dyn[];
    const int cb = blockIdx.x;
    if (cb < NCTA_L1) {
        lstm_role<H1C, 0, 0, false>(dyn, xg1, nullptr, Whh1, nullptr, nullptr,
                                    nullptr, nullptr, g_hf1[0], g_hf1[1], nullptr,
                                    flags, cb, cb);
    } else if (cb < NCTA_L1 + NCTA_L2) {
        lstm_role<H2C, H1C, 1, false>(dyn, nullptr, Wih2, Whh2, bih2, bhh2,
                                      g_hf1[0], g_hf1[1], g_hf2[0], g_hf2[1], nullptr,
                                      flags, cb - NCTA_L1, cb);
    } else {
        lstm_role<H3C, H2C, 2, true>(dyn, nullptr, Wih3, Whh3, bih3, bhh3,
                                     g_hf2[0], g_hf2[1], g_hf3[0], g_hf3[1], g_h3,
                                     flags, cb - NCTA_L1 - NCTA_L2, cb);
    }
}

// ---------------- head: deep/wide/concat/output (256 threads) ----------------
__global__ __launch_bounds__(256) void head_kernel(
    const float* __restrict__ x,
    const float* __restrict__ h3last,
    const float* __restrict__ Wd, const float* __restrict__ bd,
    const float* __restrict__ Ww, const float* __restrict__ bw,
    const float* __restrict__ Wo, const float* __restrict__ bo,
    float* __restrict__ out)
{
    const int bidx = blockIdx.x;
    const int j = threadIdx.x & 31;
    const int s = threadIdx.x >> 5;
    __shared__ float red[8][33];

    const float* xrow = x + ((size_t)bidx * TT + (TT - 1)) * DD;
    const float* wwr = Ww + (size_t)j * DD;
    float acc = 0.0f;
    const int k0 = s * (DD / 8);
#pragma unroll 4
    for (int k = k0; k < k0 + DD / 8; k += 4) {
        const float4 xv = *(const float4*)&xrow[k];
        const float4 wv = *(const float4*)&wwr[k];
        acc = fmaf(xv.x, wv.x, acc);
        acc = fmaf(xv.y, wv.y, acc);
        acc = fmaf(xv.z, wv.z, acc);
        acc = fmaf(xv.w, wv.w, acc);
    }
    red[s][j] = acc;
    __syncthreads();

    if (s == 0) {
        float wide = bw[j];
#pragma unroll
        for (int q = 0; q < 8; ++q) wide += red[q][j];
        wide = fmaxf(wide, 0.0f);

        const float* hrow = h3last + (size_t)bidx * H3C;
        const float* wdr = Wd + (size_t)j * H3C;
        float deep = bd[j];
#pragma unroll
        for (int k = 0; k < H3C; ++k) deep = fmaf(hrow[k], wdr[k], deep);
        deep = fmaxf(deep, 0.0f);

        float v = deep * Wo[j] + wide * Wo[32 + j];
#pragma unroll
        for (int off = 16; off > 0; off >>= 1)
            v += __shfl_xor_sync(0xffffffffu, v, off);
        if (j == 0) out[bidx] = v + bo[0];
    }
}

// ---------------- launch ----------------
extern "C" void kernel_launch(void* const* d_in, const int* in_sizes, int n_in,
                              void* d_out, int out_size) {
    const float* x    = (const float*)d_in[0];
    const float* Wih1 = (const float*)d_in[1];
    const float* Whh1 = (const float*)d_in[2];
    const float* bih1 = (const float*)d_in[3];
    const float* bhh1 = (const float*)d_in[4];
    const float* Wih2 = (const float*)d_in[5];
    const float* Whh2 = (const float*)d_in[6];
    const float* bih2 = (const float*)d_in[7];
    const float* bhh2 = (const float*)d_in[8];
    const float* Wih3 = (const float*)d_in[9];
    const float* Whh3 = (const float*)d_in[10];
    const float* bih3 = (const float*)d_in[11];
    const float* bhh3 = (const float*)d_in[12];
    const float* Wd   = (const float*)d_in[13];
    const float* bd   = (const float*)d_in[14];
    const float* Ww   = (const float*)d_in[15];
    const float* bw   = (const float*)d_in[16];
    const float* Wo   = (const float*)d_in[17];
    const float* bo   = (const float*)d_in[18];
    float* out = (float*)d_out;

    float *xg1, *h3;
    __nv_bfloat16 *xbf, *W1bf;
    unsigned* flags;
    cudaGetSymbolAddress((void**)&xg1,   g_xg1);
    cudaGetSymbolAddress((void**)&h3,    g_h3);
    cudaGetSymbolAddress((void**)&xbf,   g_xbf);
    cudaGetSymbolAddress((void**)&W1bf,  g_W1bf);
    cudaGetSymbolAddress((void**)&flags, g_flags);

    const int M = BB * TT;  // 32768

    prep_flags<<<7, 256>>>();

    // convert x and Wih1 to bf16 for the big GEMM
    f2bf_kernel<<<4096, 256>>>(x,    xbf,  (BB * TT * DD) / 4);
    f2bf_kernel<<<512,  256>>>(Wih1, W1bf, (4 * H1C * DD) / 4);

    // layer-1 input projection (the only big GEMM): xg1 = x @ Wih1^T + bih1 + bhh1
    {
        dim3 grid((4 * H1C) / 128, M / 128);   // N fast -> A-tile L2 reuse
        gemm_bf16_bias<<<grid, 256>>>(xbf, W1bf, bih1, bhh1, xg1, M, 4 * H1C, DD);
    }

    // fused pipelined 3-layer recurrence (needs >48KB dynamic smem)
    {
        const int dynBytes = 61440;
        static bool attrSet = false;
        cudaFuncSetAttribute(lstm_fused, cudaFuncAttributeMaxDynamicSharedMemorySize, dynBytes);
        (void)attrSet;
        lstm_fused<<<NCTA_ALL, 512, dynBytes>>>(xg1, Whh1,
                                                Wih2, Whh2, bih2, bhh2,
                                                Wih3, Whh3, bih3, bhh3,
                                                h3, flags);
    }

    // head
    head_kernel<<<BB, 256>>>(x, h3, Wd, bd, Ww, bw, Wo, bo, out);

    (void)in_sizes; (void)n_in; (void)out_size;
}

// round 6
// speedup vs baseline: 6.2592x; 1.2525x over previous
#include <cuda_runtime.h>
#include <cuda_bf16.h>
#include <cuda_fp16.h>
#include <cstdint>
#include <math.h>

// Problem dims (fixed by the reference)
#define BB 64
#define TT 512
#define DD 2048
#define H1C 256
#define H2C 128
#define H3C 64

#define NCTA_L1 32
#define NCTA_L2 16
#define NCTA_L3 8
#define NCTA_ALL 56
#define TOTS (TT + 2)

// ---------------- scratch (static device buffers; no allocation) ----------------
__device__ __align__(16) float g_xg1[(size_t)BB * TT * 4 * H1C];   // 32768 x 1024
__device__ __align__(16) __nv_bfloat16 g_xbf[(size_t)BB * TT * DD];
__device__ __align__(16) __nv_bfloat16 g_W1bf[4 * H1C * DD];
__device__ __align__(16) __half g_hf1[2][BB * H1C];   // h1 ping-pong, fp16 mma A-fragment layout
__device__ __align__(16) __half g_hf2[2][BB * H2C];
__device__ __align__(16) __half g_hf3[2][BB * H3C];
__device__ __align__(16) float g_h3[BB * H3C];        // layer-3 last h (fp32)
__device__ unsigned g_flags[NCTA_ALL * 32];           // one flag per CTA, 128B apart

// ---------------- helpers ----------------
__device__ __forceinline__ void mma_bf16(float* c, const uint32_t* a, const uint32_t* b) {
    asm volatile(
        "mma.sync.aligned.m16n8k16.row.col.f32.bf16.bf16.f32 "
        "{%0,%1,%2,%3}, {%4,%5,%6,%7}, {%8,%9}, {%0,%1,%2,%3};"
        : "+f"(c[0]), "+f"(c[1]), "+f"(c[2]), "+f"(c[3])
        : "r"(a[0]), "r"(a[1]), "r"(a[2]), "r"(a[3]), "r"(b[0]), "r"(b[1]));
}

__device__ __forceinline__ void mma_f16(float* c, const uint32_t* a, const uint32_t* b) {
    asm volatile(
        "mma.sync.aligned.m16n8k16.row.col.f32.f16.f16.f32 "
        "{%0,%1,%2,%3}, {%4,%5,%6,%7}, {%8,%9}, {%0,%1,%2,%3};"
        : "+f"(c[0]), "+f"(c[1]), "+f"(c[2]), "+f"(c[3])
        : "r"(a[0]), "r"(a[1]), "r"(a[2]), "r"(a[3]), "r"(b[0]), "r"(b[1]));
}

__device__ __forceinline__ void ldsm_x4(uint32_t* r, uint32_t addr) {
    asm volatile("ldmatrix.sync.aligned.m8n8.x4.shared.b16 {%0,%1,%2,%3}, [%4];"
                 : "=r"(r[0]), "=r"(r[1]), "=r"(r[2]), "=r"(r[3]) : "r"(addr));
}

__device__ __forceinline__ void cp_async16(uint32_t smem, const void* g) {
    asm volatile("cp.async.cg.shared.global [%0], [%1], 16;" :: "r"(smem), "l"(g));
}

__device__ __forceinline__ float rcp_(float x) {
    float r;
    asm("rcp.approx.f32 %0, %1;" : "=f"(r) : "f"(x));
    return r;
}
__device__ __forceinline__ float fast_sig(float x) {
    return rcp_(1.0f + __expf(-x));
}
__device__ __forceinline__ float fast_tanh(float x) {
    return 2.0f * rcp_(1.0f + __expf(-2.0f * x)) - 1.0f;
}

// ---------------- prep: zero flags + h fragment buffers (every replay) ----------------
__global__ void prep_zero() {
    const int i = blockIdx.x * blockDim.x + threadIdx.x;
    if (i < NCTA_ALL * 32) g_flags[i] = 0u;
    // zero all fragment ping-pong buffers (uint32 granularity)
    const int nh1 = 2 * BB * H1C / 2, nh2 = 2 * BB * H2C / 2, nh3 = 2 * BB * H3C / 2;
    uint32_t* p1 = (uint32_t*)g_hf1;
    uint32_t* p2 = (uint32_t*)g_hf2;
    uint32_t* p3 = (uint32_t*)g_hf3;
    for (int k = i; k < nh1; k += gridDim.x * blockDim.x) p1[k] = 0u;
    for (int k = i; k < nh2; k += gridDim.x * blockDim.x) p2[k] = 0u;
    for (int k = i; k < nh3; k += gridDim.x * blockDim.x) p3[k] = 0u;
}

// ---------------- fp32 -> bf16 conversion (vectorized) ----------------
__global__ void f2bf_kernel(const float* __restrict__ src, __nv_bfloat16* __restrict__ dst, int n4) {
    const int stride = gridDim.x * blockDim.x;
    __nv_bfloat162* d2 = (__nv_bfloat162*)dst;
    for (int i = blockIdx.x * blockDim.x + threadIdx.x; i < n4; i += stride) {
        const float4 v = ((const float4*)src)[i];
        d2[2 * i]     = __floats2bfloat162_rn(v.x, v.y);
        d2[2 * i + 1] = __floats2bfloat162_rn(v.z, v.w);
    }
}

// ---------------- bf16 GEMM: C[M,N] = A[M,K] * Bw[N,K]^T + b1[n] + b2[n] ----------------
// BM=128, BN=128, BK=32, 256 threads, 4-stage cp.async pipeline (dynamic smem).
__global__ __launch_bounds__(256, 1) void gemm_bf16_bias(
    const __nv_bfloat16* __restrict__ A, const __nv_bfloat16* __restrict__ Bw,
    const float* __restrict__ b1, const float* __restrict__ b2,
    float* __restrict__ C, int M, int N, int K)
{
    constexpr int BM = 128, BN = 128, BK = 32;
    constexpr int LDA = BK + 8;   // 40 elems
    constexpr int ST  = 4;
    extern __shared__ __nv_bfloat16 gsm[];
    __nv_bfloat16* As = gsm;                       // ST * BM * LDA
    __nv_bfloat16* Bs = gsm + ST * BM * LDA;       // ST * BN * LDA

    const int tid  = threadIdx.x;
    const int lane = tid & 31;
    const int warp = tid >> 5;
    const int wm   = warp & 3;
    const int wn   = warp >> 2;

    const long bm = (long)blockIdx.y * BM;   // M tile (slow dim)
    const long bn = (long)blockIdx.x * BN;   // N tile (fast dim)

    const uint32_t aBase = (uint32_t)__cvta_generic_to_shared(As);
    const uint32_t bBase = (uint32_t)__cvta_generic_to_shared(Bs);

    const int cr = tid >> 2;
    const int cs = (tid & 3) * 8;

    auto issue = [&](int st, int k0) {
#pragma unroll
        for (int i = 0; i < 2; ++i) {
            const int r = cr + i * 64;
            cp_async16(aBase + (uint32_t)(st * BM * LDA + r * LDA + cs) * 2,
                       A + (size_t)(bm + r) * K + k0 + cs);
            cp_async16(bBase + (uint32_t)(st * BN * LDA + r * LDA + cs) * 2,
                       Bw + (size_t)(bn + r) * K + k0 + cs);
        }
    };

    const int KT = K / BK;

    issue(0, 0);
    asm volatile("cp.async.commit_group;");
    issue(1, BK);
    asm volatile("cp.async.commit_group;");
    issue(2, 2 * BK);
    asm volatile("cp.async.commit_group;");

    float acc[2][8][4];
#pragma unroll
    for (int mf = 0; mf < 2; ++mf)
#pragma unroll
        for (int nt = 0; nt < 8; ++nt)
#pragma unroll
            for (int q = 0; q < 4; ++q) acc[mf][nt][q] = 0.0f;

    const int aRow = wm * 32 + (lane & 15);
    const int aColH = (lane >> 4) << 3;
    const int bRow = wn * 64 + (((lane >> 4) & 1) << 3) + (lane & 7);
    const int bColH = ((lane >> 3) & 1) << 3;

    for (int kt = 0; kt < KT; ++kt) {
        asm volatile("cp.async.wait_group 2;");
        __syncthreads();
        if (kt + 3 < KT) issue((kt + 3) & (ST - 1), (kt + 3) * BK);
        asm volatile("cp.async.commit_group;");

        const int st = kt & (ST - 1);
        const uint32_t aS = aBase + (uint32_t)(st * BM * LDA) * 2;
        const uint32_t bS = bBase + (uint32_t)(st * BN * LDA) * 2;

#pragma unroll
        for (int kf = 0; kf < 2; ++kf) {
            const int k0 = kf * 16;
            uint32_t afr[2][4];
#pragma unroll
            for (int mf = 0; mf < 2; ++mf)
                ldsm_x4(afr[mf], aS + (uint32_t)((aRow + mf * 16) * LDA + k0 + aColH) * 2);
            uint32_t bfr[4][4];
#pragma unroll
            for (int np = 0; np < 4; ++np)
                ldsm_x4(bfr[np], bS + (uint32_t)((bRow + np * 16) * LDA + k0 + bColH) * 2);
#pragma unroll
            for (int mf = 0; mf < 2; ++mf)
#pragma unroll
                for (int nt = 0; nt < 8; ++nt)
                    mma_bf16(acc[mf][nt], afr[mf], &bfr[nt >> 1][(nt & 1) * 2]);
        }
    }

#pragma unroll
    for (int mf = 0; mf < 2; ++mf) {
#pragma unroll
        for (int nt = 0; nt < 8; ++nt) {
            const long r0 = bm + wm * 32 + mf * 16 + (lane >> 2);
            const long c0 = bn + wn * 64 + nt * 8 + 2 * (lane & 3);
            const float bias0 = b1[c0] + b2[c0];
            const float bias1 = b1[c0 + 1] + b2[c0 + 1];
            C[r0 * N + c0]           = acc[mf][nt][0] + bias0;
            C[r0 * N + c0 + 1]       = acc[mf][nt][1] + bias1;
            C[(r0 + 8) * N + c0]     = acc[mf][nt][2] + bias0;
            C[(r0 + 8) * N + c0 + 1] = acc[mf][nt][3] + bias1;
        }
    }
}

// ---------------- fused 3-layer pipelined LSTM (fp16 mma, weights in registers) -------
// HC = 8 units per CTA, 512 threads, 16 warps = 4 mi x 4 split-K slices.
// h exchanged between CTAs as fp16 A-fragment arrays in L2 (cp.async staged to SMEM).
template <int H, int KP, int FIRST, bool LAST_ONLY>
__device__ __forceinline__ void lstm_role2(
    char* dyn,
    const float* __restrict__ xg,
    const float* __restrict__ Wih,
    const float* __restrict__ Whh,
    const float* __restrict__ bih,
    const float* __restrict__ bhh,
    const __half* __restrict__ hfp0, const __half* __restrict__ hfp1,
    __half* __restrict__ hfo0, __half* __restrict__ hfo1,
    float* __restrict__ hlast,
    unsigned* __restrict__ flags,
    int ctaLocal, int myflag)
{
    constexpr int HC   = 8;
    constexpr int GSW  = 34;                 // gS row stride (32 cols + pad)
    constexpr int KB_R = H / 16;
    constexpr int KB_P = (KP > 0) ? KP / 16 : 0;
    constexpr int KBT  = KB_P + KB_R;
    constexpr int KS   = KBT / 4;            // kbs per split-K slice
    static_assert(KS * 4 == KBT, "splitK");

    __half*   Af   = (__half*)dyn;                              // KBT*2048 bytes
    float*    gS   = (float*)(dyn + KBT * 2048);                // 4 slabs * 64 * GSW
    uint32_t* hS32 = (uint32_t*)(dyn + KBT * 2048 + 4 * 64 * GSW * 4);  // 256 u32

    const int tid  = threadIdx.x;
    const int lane = tid & 31;
    const int w    = tid >> 5;
    const int grp  = lane >> 2;
    const int th4  = lane & 3;
    const int h0   = ctaLocal * HC;

    const uint32_t AfB = (uint32_t)__cvta_generic_to_shared(Af);

    // ---- build weight B-fragments in registers (once) ----
    const int mi = w & 3;
    const int ks = w >> 2;
    uint32_t bw[KS][4][2];
    {
        const int col  = (lane >> 2);            // within ni*8 block
        const int kk0  = (lane & 3) * 2;
#pragma unroll
        for (int q = 0; q < KS; ++q) {
            const int kbg = ks * KS + q;
#pragma unroll
            for (int ni = 0; ni < 4; ++ni) {
                const int coln = ni * 8 + col;
                const int grow = (coln >> 3) * H + h0 + (coln & 7);
#pragma unroll
                for (int j = 0; j < 2; ++j) {
                    float w0, w1;
                    if (KP > 0 && kbg < KB_P) {
                        const float* p = Wih + (size_t)grow * KP + kbg * 16 + j * 8 + kk0;
                        w0 = p[0]; w1 = p[1];
                    } else {
                        const int kbr = kbg - KB_P;
                        const float* p = Whh + (size_t)grow * H + kbr * 16 + j * 8 + kk0;
                        w0 = p[0]; w1 = p[1];
                    }
                    __half2 hh = __floats2half2_rn(w0, w1);
                    bw[q][ni][j] = *reinterpret_cast<uint32_t*>(&hh);
                }
            }
        }
    }

    // ---- elementwise ownership: thread -> (batch b, unit jj) ----
    const int b   = tid >> 3;   // 0..63
    const int jj  = tid & 7;    // 0..7
    const int kme = h0 + jj;
    const int r_w = b & 15;
    const int miw = b >> 4;
    // local hS position for my h value
    const int hSidx = (((miw * 32 + ((r_w & 7) * 4 + (jj >> 1))) * 2 + (r_w >> 3)) * 2) + (jj & 1);

    float c = 0.0f;
    float xi, xf, xgv, xo;
    if (KP == 0) {
        const float* xp = xg + ((size_t)b * TT) * (4 * H) + kme;
        xi = xp[0]; xf = xp[H]; xgv = xp[2 * H]; xo = xp[3 * H];
    } else {
        xi  = bih[kme]         + bhh[kme];
        xf  = bih[H + kme]     + bhh[H + kme];
        xgv = bih[2 * H + kme] + bhh[2 * H + kme];
        xo  = bih[3 * H + kme] + bhh[3 * H + kme];
    }

    // h output -> global fragment position constants
    const int kbG   = ctaLocal >> 1;   // which k16 block my units live in
    const int khalf = ctaLocal & 1;    // which reg pair (k 0..7 or 8..15)

    __syncthreads();

    for (int s = 0; s < TOTS; ++s) {
        const int t = s - FIRST;
        const bool active = (t >= 0) && (t < TT);

        if (active) {
            // ---- stage A fragments (proj h then rec h) via cp.async ----
            const __half* srcP = (t & 1) ? hfp1 : hfp0;
            const __half* srcR = (t & 1) ? hfo0 : hfo1;
            for (int i = tid; i < KBT * 128; i += 512) {
                const __half* src = (KP > 0 && i < KB_P * 128)
                                        ? (srcP + (size_t)i * 8)
                                        : (srcR + (size_t)(i - KB_P * 128) * 8);
                cp_async16(AfB + (uint32_t)i * 16, src);
            }
            asm volatile("cp.async.commit_group;");
            asm volatile("cp.async.wait_group 0;");
        }
        __syncthreads();

        if (active) {
            // ---- mma: warp (mi, ks) covers all 4 ni over its KS k-blocks ----
            float acc[4][4];
#pragma unroll
            for (int ni = 0; ni < 4; ++ni)
#pragma unroll
                for (int q = 0; q < 4; ++q) acc[ni][q] = 0.0f;

#pragma unroll
            for (int q = 0; q < KS; ++q) {
                const int kb = ks * KS + q;
                const float4 a = *(const float4*)(Af + ((size_t)(kb * 4 + mi) * 32 + lane) * 8);
                uint32_t au[4] = {__float_as_uint(a.x), __float_as_uint(a.y),
                                  __float_as_uint(a.z), __float_as_uint(a.w)};
#pragma unroll
                for (int ni = 0; ni < 4; ++ni)
                    mma_f16(acc[ni], au, bw[q][ni]);
            }

            float* gsl = gS + ks * (64 * GSW);
            const int rr = mi * 16 + grp;
#pragma unroll
            for (int ni = 0; ni < 4; ++ni) {
                const int cc = ni * 8 + 2 * th4;
                gsl[rr * GSW + cc]           = acc[ni][0];
                gsl[rr * GSW + cc + 1]       = acc[ni][1];
                gsl[(rr + 8) * GSW + cc]     = acc[ni][2];
                gsl[(rr + 8) * GSW + cc + 1] = acc[ni][3];
            }
        }
        __syncthreads();

        if (active) {
            float pi = xi, pf = xf, pg = xgv, po = xo;
#pragma unroll
            for (int sl = 0; sl < 4; ++sl) {
                const float* gr = gS + sl * (64 * GSW) + b * GSW;
                pi += gr[jj];
                pf += gr[HC + jj];
                pg += gr[2 * HC + jj];
                po += gr[3 * HC + jj];
            }
            const float iv = fast_sig(pi);
            const float fv = fast_sig(pf);
            const float gv = fast_tanh(pg);
            const float ov = fast_sig(po);
            c = fv * c + iv * gv;
            const float h = ov * fast_tanh(c);

            ((__half*)hS32)[hSidx] = __float2half(h);

            if (LAST_ONLY && t == TT - 1)
                hlast[(size_t)b * H + kme] = h;

            if (KP == 0 && t + 1 < TT) {
                const float* xp = xg + ((size_t)b * TT + (t + 1)) * (4 * H) + kme;
                xi = xp[0]; xf = xp[H]; xgv = xp[2 * H]; xo = xp[3 * H];
            }
        }
        __syncthreads();

        // ---- coalesced-ish copy of my 1KB of h fragments to global ----
        if (active && tid < 256) {
            const int reg   = tid & 1;
            const int lane5 = (tid >> 1) & 31;
            const int mic   = tid >> 6;
            uint32_t* G = (uint32_t*)((t & 1) ? hfo1 : hfo0);
            G[((size_t)(kbG * 4 + mic) * 32 + lane5) * 4 + khalf * 2 + reg] =
                hS32[(mic * 32 + lane5) * 2 + reg];
        }
        __syncthreads();

        // ---- distributed flag barrier ----
        if (tid == 0) {
            asm volatile("st.release.gpu.global.u32 [%0], %1;"
                         :: "l"(flags + myflag * 32), "r"((unsigned)(s + 1)) : "memory");
        }
        if (tid < NCTA_ALL) {
            unsigned v;
            const unsigned tgt = (unsigned)(s + 1);
            unsigned* fp = flags + tid * 32;
            do {
                asm volatile("ld.acquire.gpu.global.u32 %0, [%1];" : "=r"(v) : "l"(fp) : "memory");
            } while (v < tgt);
        }
        __syncthreads();
    }
}

__global__ __launch_bounds__(512, 1) void lstm_fused(
    const float* __restrict__ xg1,
    const float* __restrict__ Whh1,
    const float* __restrict__ Wih2, const float* __restrict__ Whh2,
    const float* __restrict__ bih2, const float* __restrict__ bhh2,
    const float* __restrict__ Wih3, const float* __restrict__ Whh3,
    const float* __restrict__ bih3, const float* __restrict__ bhh3,
    float* __restrict__ h3out, unsigned* __restrict__ flags)
{
    extern __shared__ char dynls[];
    const int cb = blockIdx.x;
    if (cb < NCTA_L1) {
        lstm_role2<H1C, 0, 0, false>(dynls, xg1, nullptr, Whh1, nullptr, nullptr,
                                     nullptr, nullptr, g_hf1[0], g_hf1[1], nullptr,
                                     flags, cb, cb);
    } else if (cb < NCTA_L1 + NCTA_L2) {
        lstm_role2<H2C, H1C, 1, false>(dynls, nullptr, Wih2, Whh2, bih2, bhh2,
                                       g_hf1[0], g_hf1[1], g_hf2[0], g_hf2[1], nullptr,
                                       flags, cb - NCTA_L1, cb);
    } else {
        lstm_role2<H3C, H2C, 2, true>(dynls, nullptr, Wih3, Whh3, bih3, bhh3,
                                      g_hf2[0], g_hf2[1], g_hf3[0], g_hf3[1], h3out,
                                      flags, cb - NCTA_L1 - NCTA_L2, cb);
    }
}

// ---------------- head: deep/wide/concat/output (256 threads) ----------------
__global__ __launch_bounds__(256) void head_kernel(
    const float* __restrict__ x,
    const float* __restrict__ h3last,
    const float* __restrict__ Wd, const float* __restrict__ bd,
    const float* __restrict__ Ww, const float* __restrict__ bw,
    const float* __restrict__ Wo, const float* __restrict__ bo,
    float* __restrict__ out)
{
    const int bidx = blockIdx.x;
    const int j = threadIdx.x & 31;
    const int s = threadIdx.x >> 5;
    __shared__ float red[8][33];

    const float* xrow = x + ((size_t)bidx * TT + (TT - 1)) * DD;
    const float* wwr = Ww + (size_t)j * DD;
    float acc = 0.0f;
    const int k0 = s * (DD / 8);
#pragma unroll 4
    for (int k = k0; k < k0 + DD / 8; k += 4) {
        const float4 xv = *(const float4*)&xrow[k];
        const float4 wv = *(const float4*)&wwr[k];
        acc = fmaf(xv.x, wv.x, acc);
        acc = fmaf(xv.y, wv.y, acc);
        acc = fmaf(xv.z, wv.z, acc);
        acc = fmaf(xv.w, wv.w, acc);
    }
    red[s][j] = acc;
    __syncthreads();

    if (s == 0) {
        float wide = bw[j];
#pragma unroll
        for (int q = 0; q < 8; ++q) wide += red[q][j];
        wide = fmaxf(wide, 0.0f);

        const float* hrow = h3last + (size_t)bidx * H3C;
        const float* wdr = Wd + (size_t)j * H3C;
        float deep = bd[j];
#pragma unroll
        for (int k = 0; k < H3C; ++k) deep = fmaf(hrow[k], wdr[k], deep);
        deep = fmaxf(deep, 0.0f);

        float v = deep * Wo[j] + wide * Wo[32 + j];
#pragma unroll
        for (int off = 16; off > 0; off >>= 1)
            v += __shfl_xor_sync(0xffffffffu, v, off);
        if (j == 0) out[bidx] = v + bo[0];
    }
}

// ---------------- launch ----------------
extern "C" void kernel_launch(void* const* d_in, const int* in_sizes, int n_in,
                              void* d_out, int out_size) {
    const float* x    = (const float*)d_in[0];
    const float* Wih1 = (const float*)d_in[1];
    const float* Whh1 = (const float*)d_in[2];
    const float* bih1 = (const float*)d_in[3];
    const float* bhh1 = (const float*)d_in[4];
    const float* Wih2 = (const float*)d_in[5];
    const float* Whh2 = (const float*)d_in[6];
    const float* bih2 = (const float*)d_in[7];
    const float* bhh2 = (const float*)d_in[8];
    const float* Wih3 = (const float*)d_in[9];
    const float* Whh3 = (const float*)d_in[10];
    const float* bih3 = (const float*)d_in[11];
    const float* bhh3 = (const float*)d_in[12];
    const float* Wd   = (const float*)d_in[13];
    const float* bd   = (const float*)d_in[14];
    const float* Ww   = (const float*)d_in[15];
    const float* bw   = (const float*)d_in[16];
    const float* Wo   = (const float*)d_in[17];
    const float* bo   = (const float*)d_in[18];
    float* out = (float*)d_out;

    float *xg1, *h3;
    __nv_bfloat16 *xbf, *W1bf;
    unsigned* flags;
    cudaGetSymbolAddress((void**)&xg1,   g_xg1);
    cudaGetSymbolAddress((void**)&h3,    g_h3);
    cudaGetSymbolAddress((void**)&xbf,   g_xbf);
    cudaGetSymbolAddress((void**)&W1bf,  g_W1bf);
    cudaGetSymbolAddress((void**)&flags, g_flags);

    const int M = BB * TT;  // 32768

    prep_zero<<<60, 512>>>();

    // convert x and Wih1 to bf16 for the big GEMM
    f2bf_kernel<<<4096, 256>>>(x,    xbf,  (BB * TT * DD) / 4);
    f2bf_kernel<<<512,  256>>>(Wih1, W1bf, (4 * H1C * DD) / 4);

    // layer-1 input projection: xg1 = x @ Wih1^T + bih1 + bhh1  (4-stage pipeline)
    {
        const int gsmem = 4 * (128 + 128) * 40 * 2;  // 81920 B
        cudaFuncSetAttribute(gemm_bf16_bias, cudaFuncAttributeMaxDynamicSharedMemorySize, gsmem);
        dim3 grid((4 * H1C) / 128, M / 128);
        gemm_bf16_bias<<<grid, 256, gsmem>>>(xbf, W1bf, bih1, bhh1, xg1, M, 4 * H1C, DD);
    }

    // fused pipelined 3-layer recurrence
    {
        // max role smem: layer2 = 24*2048 + 4*64*34*4 + 1024 = 84992 B
        const int dynBytes = 84992;
        cudaFuncSetAttribute(lstm_fused, cudaFuncAttributeMaxDynamicSharedMemorySize, dynBytes);
        lstm_fused<<<NCTA_ALL, 512, dynBytes>>>(xg1, Whh1,
                                                Wih2, Whh2, bih2, bhh2,
                                                Wih3, Whh3, bih3, bhh3,
                                                h3, flags);
    }

    // head
    head_kernel<<<BB, 256>>>(x, h3, Wd, bd, Ww, bw, Wo, bo, out);

    (void)in_sizes; (void)n_in; (void)out_size;
}